// round 13
// baseline (speedup 1.0000x reference)
#include <cuda_runtime.h>
#include <cuda_bf16.h>
#include <cstdint>

#define NN 300000
#define EE 600000
#define HH 128
#define GG 8192

// ---------------- scratch (device globals: allocation-free) ----------------
__device__ float g_P[(size_t)NN * HH];    // prev-layer raw output (y2 pre-BN)
__device__ float g_HIN[(size_t)NN * HH];  // h_in
__device__ float g_Y1[(size_t)NN * HH];   // y1 (pre-BN1 GEMM1 output)
__device__ float g_pool[(size_t)GG * HH];
__device__ float g_stats[4 * HH];         // [sum1, sumsq1 | sum2, sumsq2]
__device__ __nv_bfloat16 g_Wh[10 * HH * HH];
__device__ __nv_bfloat16 g_Wl[10 * HH * HH];
// CSR by row (payload cidx) for bond sums; CSC by col (payload row) for aggr gather
__device__ int g_cnt[NN],  g_cur[NN],  g_off[NN + 1];
__device__ int g_cnt2[NN], g_cur2[NN], g_off2[NN + 1];
__device__ unsigned int g_pack[EE];    // cidx (bond table index)
__device__ int g_pack2[EE];            // src row
// precombined bond tables: [5][216][128]
__device__ float g_ctab[5 * 216 * HH];

__device__ __forceinline__ void red_add_v4(float* p, float4 v) {
    asm volatile("red.global.add.v4.f32 [%0], {%1,%2,%3,%4};"
                 :: "l"(p), "f"(v.x), "f"(v.y), "f"(v.z), "f"(v.w) : "memory");
}
__device__ __forceinline__ uint32_t smem_u32(const void* p) {
    uint32_t a;
    asm("{ .reg .u64 t; cvta.to.shared.u64 t, %1; cvt.u32.u64 %0, t; }" : "=r"(a) : "l"(p));
    return a;
}
__device__ __forceinline__ void ldsm4(uint32_t* r, uint32_t addr) {
    asm volatile("ldmatrix.sync.aligned.m8n8.x4.shared.b16 {%0,%1,%2,%3}, [%4];"
                 : "=r"(r[0]), "=r"(r[1]), "=r"(r[2]), "=r"(r[3]) : "r"(addr));
}
__device__ __forceinline__ void mma16816(float* d, const uint32_t* a, const uint32_t* b) {
    asm volatile("mma.sync.aligned.m16n8k16.row.col.f32.bf16.bf16.f32 "
                 "{%0,%1,%2,%3}, {%4,%5,%6,%7}, {%8,%9}, {%0,%1,%2,%3};"
                 : "+f"(d[0]), "+f"(d[1]), "+f"(d[2]), "+f"(d[3])
                 : "r"(a[0]), "r"(a[1]), "r"(a[2]), "r"(a[3]), "r"(b[0]), "r"(b[1]));
}

// ---------------- setup kernels ----------------
__global__ void k_init() {
    size_t stride = (size_t)gridDim.x * blockDim.x;
    size_t i0 = (size_t)blockIdx.x * blockDim.x + threadIdx.x;
    for (size_t i = i0; i < (size_t)NN; i += stride) {
        g_cnt[i] = 0; g_cur[i] = 0; g_cnt2[i] = 0; g_cur2[i] = 0;
    }
    for (size_t i = i0; i < (size_t)GG * HH; i += stride) g_pool[i] = 0.f;
}

__global__ void k_prepw(const float* __restrict__ w1, const float* __restrict__ w2) {
    int l = blockIdx.y;   // 0..9
    const float* W = (l < 5) ? (w1 + (size_t)l * HH * HH) : (w2 + (size_t)(l - 5) * HH * HH);
    int slot = (l < 5) ? (2 * l) : (2 * (l - 5) + 1);
    int q = blockIdx.x * 256 + threadIdx.x;
    int k = q >> 5, n0 = (q & 31) * 4;
    float4 w = *(const float4*)(W + (size_t)k * HH + n0);
    float wv[4] = {w.x, w.y, w.z, w.w};
#pragma unroll
    for (int j = 0; j < 4; j++) {
        __nv_bfloat16 h = __float2bfloat16(wv[j]);
        size_t o = (size_t)slot * HH * HH + (size_t)(n0 + j) * HH + k;
        g_Wh[o] = h;
        g_Wl[o] = __float2bfloat16(wv[j] - __bfloat162float(h));
    }
}

__global__ void k_prepbond(const float* __restrict__ bemb) {
    int c = blockIdx.x;   // 0..215
    int l = blockIdx.y;   // 0..4
    int h = threadIdx.x;  // 0..127
    int a0 = c / 36, a1 = (c / 6) % 6, a2 = c % 6;
    const float* b = bemb + (size_t)l * 3 * 8 * HH;
    g_ctab[((size_t)l * 216 + c) * HH + h] =
        b[(size_t)(0 * 8 + a0) * HH + h] + b[(size_t)(1 * 8 + a1) * HH + h]
        + b[(size_t)(2 * 8 + a2) * HH + h];
}

__global__ void k_cnt(const int* __restrict__ row, const int* __restrict__ col) {
    int e = blockIdx.x * blockDim.x + threadIdx.x;
    if (e < EE) {
        atomicAdd(&g_cnt[__ldg(row + e)], 1);
        atomicAdd(&g_cnt2[__ldg(col + e)], 1);
    }
}

// exclusive scan: block 0 -> (cnt,off), block 1 -> (cnt2,off2)
__global__ void k_scan() {
    __shared__ int bs[1024];
    const int* cnt = (blockIdx.x == 0) ? g_cnt : g_cnt2;
    int* off = (blockIdx.x == 0) ? g_off : g_off2;
    const int t = threadIdx.x;
    const int C = (NN + 1023) / 1024;   // 293
    int base = t * C;
    int s = 0;
    for (int i = 0; i < C; i++) {
        int idx = base + i;
        if (idx < NN) s += cnt[idx];
    }
    bs[t] = s;
    __syncthreads();
    for (int o = 1; o < 1024; o <<= 1) {
        int u = (t >= o) ? bs[t - o] : 0;
        __syncthreads();
        bs[t] += u;
        __syncthreads();
    }
    int run = bs[t] - s;
    for (int i = 0; i < C; i++) {
        int idx = base + i;
        if (idx < NN) { off[idx] = run; run += cnt[idx]; }
    }
    if (t == 1023) off[NN] = EE;
}

__global__ void k_fill(const int* __restrict__ row, const int* __restrict__ col,
                       const int* __restrict__ eattr) {
    int e = blockIdx.x * blockDim.x + threadIdx.x;
    if (e >= EE) return;
    int r = __ldg(row + e);
    int c = __ldg(col + e);
    int a0 = __ldg(eattr + e * 3 + 0);
    int a1 = __ldg(eattr + e * 3 + 1);
    int a2 = __ldg(eattr + e * 3 + 2);
    int pos = g_off[r] + atomicAdd(&g_cur[r], 1);
    g_pack[pos] = (unsigned int)(a0 * 36 + a1 * 6 + a2);
    int pos2 = g_off2[c] + atomicAdd(&g_cur2[c], 1);
    g_pack2[pos2] = r;
}

// ---------------- node kernel (bond sum + act(prev) + hin) ----------------
template<int FIRST>
__global__ void __launch_bounds__(256)
k_node(int layer, const float* __restrict__ bg, const float* __restrict__ bb,
       const int* __restrict__ x, const float* __restrict__ aemb) {
    __shared__ float s_sc[HH], s_sh[HH];
    const int tid = threadIdx.x;
    if (blockIdx.x == 0 && tid < 2 * HH) g_stats[tid] = 0.f;   // zero slot0
    if (!FIRST) {
        if (tid < HH) {
            float mu  = g_stats[2 * HH + tid] * (1.f / (float)NN);
            float msq = g_stats[3 * HH + tid] * (1.f / (float)NN);
            float rstd = rsqrtf(msq - mu * mu + 1e-5f);
            float s = __ldg(bg + tid) * rstd;
            s_sc[tid] = s;
            s_sh[tid] = __ldg(bb + tid) - s * mu;
        }
        __syncthreads();
    }
    const int n = blockIdx.x * 8 + (tid >> 5);
    if (n >= NN) return;
    const int c4 = (tid & 31) << 2;
    const float* ctab = g_ctab + (size_t)layer * 216 * HH;
    const int e0 = __ldg(&g_off[n]), e1 = __ldg(&g_off[n + 1]);
    const float inv = 1.f / ((float)(e1 - e0) + 1.f);

    float4 bsum = make_float4(0.f, 0.f, 0.f, 0.f);
    for (int e = e0; e < e1; e++) {
        unsigned int ci = __ldg(&g_pack[e]);
        const float4 t = *(const float4*)(ctab + (size_t)ci * HH + c4);
        bsum.x += t.x; bsum.y += t.y; bsum.z += t.z; bsum.w += t.w;
    }
    float4 p;
    if (FIRST) {
        p = make_float4(0.f, 0.f, 0.f, 0.f);
#pragma unroll
        for (int f = 0; f < 9; f++) {
            int xi = __ldg(x + n * 9 + f);
            const float4 e = *(const float4*)(aemb + ((size_t)(f * 128 + xi) * HH + c4));
            p.x += e.x; p.y += e.y; p.z += e.z; p.w += e.w;
        }
    } else {
        p = *(const float4*)(g_P + (size_t)n * HH + c4);
        p.x = fmaxf(fmaf(s_sc[c4 + 0], p.x, s_sh[c4 + 0]), 0.f);
        p.y = fmaxf(fmaf(s_sc[c4 + 1], p.y, s_sh[c4 + 1]), 0.f);
        p.z = fmaxf(fmaf(s_sc[c4 + 2], p.z, s_sh[c4 + 2]), 0.f);
        p.w = fmaxf(fmaf(s_sc[c4 + 3], p.w, s_sh[c4 + 3]), 0.f);
    }
    float4 h;
    h.x = fmaf(bsum.x, inv, p.x);
    h.y = fmaf(bsum.y, inv, p.y);
    h.z = fmaf(bsum.z, inv, p.z);
    h.w = fmaf(bsum.w, inv, p.w);
    *(float4*)(g_HIN + (size_t)n * HH + c4) = h;
}

// ---------------- HMMA bf16-split GEMM, M-tile 64, two-pass B, 3 CTAs/SM ----
// pass1: B=Wh, acc += Ah*B + Al*B;  pass2: B=Wl, acc += Ah*B.  (R10 structure)
#define PAD 136
#define GEMM_SMEM 71680

template<int MODE>
__global__ void __launch_bounds__(256, 3)
k_mma(int wslot, const float* __restrict__ bias,
      const float* __restrict__ epsp,
      const float* __restrict__ bg, const float* __restrict__ bb) {
    extern __shared__ char dsm[];
    __shared__ float s_sc[HH], s_sh[HH];

    const uint32_t su = smem_u32(dsm);
    const uint32_t Ah_u = su, Al_u = su + 17408;
    const uint32_t B_u = su + 34816;
    __nv_bfloat16* Ah = (__nv_bfloat16*)dsm;
    __nv_bfloat16* Al = (__nv_bfloat16*)(dsm + 17408);
    __nv_bfloat16* Bs = (__nv_bfloat16*)(dsm + 34816);
    float* sS = (float*)(dsm + 69632);   // [2][128]
    float* sQ = (float*)(dsm + 70656);   // [2][128]

    const int tid = threadIdx.x;
    const int wid = tid >> 5, lane = tid & 31;
    const int wm = wid & 1, wn = wid >> 1;
    const int m0 = blockIdx.x * 64;

    if (MODE == 1 && blockIdx.x == 0 && tid < 2 * HH)
        g_stats[2 * HH + tid] = 0.f;   // zero slot1 for upcoming GEMM2
    if (MODE == 2 && tid < HH) {
        float mu  = g_stats[tid] * (1.f / (float)NN);
        float msq = g_stats[HH + tid] * (1.f / (float)NN);
        float rstd = rsqrtf(msq - mu * mu + 1e-5f);
        float s = __ldg(bg + tid) * rstd;
        s_sc[tid] = s;
        s_sh[tid] = __ldg(bb + tid) - s * mu;
    }
    const float epsl = (MODE == 1) ? (1.f + __ldg(epsp)) : 0.f;
    if (MODE == 2) __syncthreads();

    // ---- pass-1 W tile: hi ----
    const __nv_bfloat16* wh = g_Wh + (size_t)wslot * HH * HH;
    const __nv_bfloat16* wl = g_Wl + (size_t)wslot * HH * HH;
#pragma unroll
    for (int it = 0; it < 8; it++) {
        int q = it * 256 + tid;
        int n = q >> 4, k0 = (q & 15) * 8;
        *(uint4*)(Bs + n * PAD + k0) = *(const uint4*)(wh + n * HH + k0);
    }

    // ---- A: load + transform + split ----
    const int w = tid >> 5;
    const int c0 = (tid & 31) * 4;
    if (MODE == 1) {
        // two groups of 4 rows; within a group all loads are independent (MLP)
#pragma unroll
        for (int g = 0; g < 2; g++) {
            int rg[4], ea[4], eb[4];
#pragma unroll
            for (int i = 0; i < 4; i++) {
                rg[i] = m0 + (g * 4 + i) * 8 + w;
                bool ok = rg[i] < NN;
                ea[i] = ok ? __ldg(&g_off2[rg[i]]) : 0;
                eb[i] = ok ? __ldg(&g_off2[rg[i] + 1]) : 0;
            }
            int src[4][4];
#pragma unroll
            for (int i = 0; i < 4; i++) {
                int d = eb[i] - ea[i];
#pragma unroll
                for (int j = 0; j < 4; j++) {
                    int idx = ea[i] + ((j < d) ? j : 0);
                    src[i][j] = (d > 0) ? __ldg(&g_pack2[idx]) : 0;
                }
            }
            float4 vv[4];
#pragma unroll
            for (int i = 0; i < 4; i++) {
                float4 v = make_float4(0.f, 0.f, 0.f, 0.f);
                if (rg[i] < NN) {
                    float4 hv = *(const float4*)(g_HIN + (size_t)rg[i] * HH + c0);
                    v.x = epsl * hv.x; v.y = epsl * hv.y;
                    v.z = epsl * hv.z; v.w = epsl * hv.w;
                }
                vv[i] = v;
            }
#pragma unroll
            for (int j = 0; j < 4; j++) {
#pragma unroll
                for (int i = 0; i < 4; i++) {
                    if (j < eb[i] - ea[i]) {
                        float4 a = *(const float4*)(g_HIN + (size_t)src[i][j] * HH + c0);
                        vv[i].x += a.x; vv[i].y += a.y;
                        vv[i].z += a.z; vv[i].w += a.w;
                    }
                }
            }
#pragma unroll
            for (int i = 0; i < 4; i++) {
                for (int e = ea[i] + 4; e < eb[i]; e++) {
                    int s0 = __ldg(&g_pack2[e]);
                    float4 a = *(const float4*)(g_HIN + (size_t)s0 * HH + c0);
                    vv[i].x += a.x; vv[i].y += a.y;
                    vv[i].z += a.z; vv[i].w += a.w;
                }
            }
#pragma unroll
            for (int i = 0; i < 4; i++) {
                int r = (g * 4 + i) * 8 + w;
                float fv[4] = {vv[i].x, vv[i].y, vv[i].z, vv[i].w};
                __nv_bfloat16 hb[4], lb[4];
#pragma unroll
                for (int j = 0; j < 4; j++) {
                    hb[j] = __float2bfloat16(fv[j]);
                    lb[j] = __float2bfloat16(fv[j] - __bfloat162float(hb[j]));
                }
                *(uint2*)(Ah + r * PAD + c0) = *(uint2*)hb;
                *(uint2*)(Al + r * PAD + c0) = *(uint2*)lb;
            }
        }
    } else {
#pragma unroll
        for (int it = 0; it < 8; it++) {
            int r = it * 8 + w;
            int grow = m0 + r;
            float4 v = make_float4(0.f, 0.f, 0.f, 0.f);
            if (grow < NN) {
                float4 y = *(const float4*)(g_Y1 + (size_t)grow * HH + c0);
                v.x = fmaxf(fmaf(s_sc[c0 + 0], y.x, s_sh[c0 + 0]), 0.f);
                v.y = fmaxf(fmaf(s_sc[c0 + 1], y.y, s_sh[c0 + 1]), 0.f);
                v.z = fmaxf(fmaf(s_sc[c0 + 2], y.z, s_sh[c0 + 2]), 0.f);
                v.w = fmaxf(fmaf(s_sc[c0 + 3], y.w, s_sh[c0 + 3]), 0.f);
            }
            float fv[4] = {v.x, v.y, v.z, v.w};
            __nv_bfloat16 hb[4], lb[4];
#pragma unroll
            for (int j = 0; j < 4; j++) {
                hb[j] = __float2bfloat16(fv[j]);
                lb[j] = __float2bfloat16(fv[j] - __bfloat162float(hb[j]));
            }
            *(uint2*)(Ah + r * PAD + c0) = *(uint2*)hb;
            *(uint2*)(Al + r * PAD + c0) = *(uint2*)lb;
        }
    }
    __syncthreads();

    float acc[2][4][4];
#pragma unroll
    for (int mi = 0; mi < 2; mi++)
#pragma unroll
        for (int nb = 0; nb < 4; nb++)
#pragma unroll
            for (int j = 0; j < 4; j++) acc[mi][nb][j] = 0.f;

    const int aRow = wm * 32 + (lane & 15);
    const int aKs = (lane >> 4) * 8;
    const int bN = wn * 32 + (lane >> 4) * 8 + (lane & 7);
    const int bKs = ((lane >> 3) & 1) * 8;

    // ---- pass 1: acc += Ah*Bh + Al*Bh ----
#pragma unroll
    for (int ks = 0; ks < 8; ks++) {
        uint32_t ah[2][4], al[2][4], bbq[2][4];
#pragma unroll
        for (int mi = 0; mi < 2; mi++) {
            uint32_t ra = (uint32_t)(((aRow + mi * 16) * PAD + ks * 16 + aKs) * 2);
            ldsm4(ah[mi], Ah_u + ra);
            ldsm4(al[mi], Al_u + ra);
        }
#pragma unroll
        for (int nb2 = 0; nb2 < 2; nb2++) {
            uint32_t rb = (uint32_t)(((bN + nb2 * 16) * PAD + ks * 16 + bKs) * 2);
            ldsm4(bbq[nb2], B_u + rb);
        }
#pragma unroll
        for (int mi = 0; mi < 2; mi++)
#pragma unroll
            for (int nb = 0; nb < 4; nb++) {
                const uint32_t* bp = &bbq[nb >> 1][(nb & 1) * 2];
                mma16816(acc[mi][nb], ah[mi], bp);
                mma16816(acc[mi][nb], al[mi], bp);
            }
    }
    __syncthreads();   // all warps done reading Bh

    // ---- pass-2 W tile: lo ----
#pragma unroll
    for (int it = 0; it < 8; it++) {
        int q = it * 256 + tid;
        int n = q >> 4, k0 = (q & 15) * 8;
        *(uint4*)(Bs + n * PAD + k0) = *(const uint4*)(wl + n * HH + k0);
    }
    __syncthreads();

    // ---- pass 2: acc += Ah*Bl ----
#pragma unroll
    for (int ks = 0; ks < 8; ks++) {
        uint32_t ah[2][4], bbq[2][4];
#pragma unroll
        for (int mi = 0; mi < 2; mi++) {
            uint32_t ra = (uint32_t)(((aRow + mi * 16) * PAD + ks * 16 + aKs) * 2);
            ldsm4(ah[mi], Ah_u + ra);
        }
#pragma unroll
        for (int nb2 = 0; nb2 < 2; nb2++) {
            uint32_t rb = (uint32_t)(((bN + nb2 * 16) * PAD + ks * 16 + bKs) * 2);
            ldsm4(bbq[nb2], B_u + rb);
        }
#pragma unroll
        for (int mi = 0; mi < 2; mi++)
#pragma unroll
            for (int nb = 0; nb < 4; nb++)
                mma16816(acc[mi][nb], ah[mi], &bbq[nb >> 1][(nb & 1) * 2]);
    }

    // ---- epilogue: bias, store, per-column stats ----
    float* outp = (MODE == 1) ? g_Y1 : g_P;
    float cs[4][2], cq[4][2];
#pragma unroll
    for (int nb = 0; nb < 4; nb++) { cs[nb][0] = cs[nb][1] = 0.f; cq[nb][0] = cq[nb][1] = 0.f; }
    float bse[4][2];
#pragma unroll
    for (int nb = 0; nb < 4; nb++) {
        int c = wn * 32 + nb * 8 + (lane & 3) * 2;
        bse[nb][0] = __ldg(bias + c);
        bse[nb][1] = __ldg(bias + c + 1);
    }
#pragma unroll
    for (int mi = 0; mi < 2; mi++) {
        int r0 = m0 + wm * 32 + mi * 16 + (lane >> 2);
        int r1 = r0 + 8;
        bool v0 = r0 < NN, v1 = r1 < NN;
#pragma unroll
        for (int nb = 0; nb < 4; nb++) {
            int c = wn * 32 + nb * 8 + (lane & 3) * 2;
            float o0 = acc[mi][nb][0] + bse[nb][0];
            float o1 = acc[mi][nb][1] + bse[nb][1];
            float o2 = acc[mi][nb][2] + bse[nb][0];
            float o3 = acc[mi][nb][3] + bse[nb][1];
            if (v0) {
                *(float2*)(outp + (size_t)r0 * HH + c) = make_float2(o0, o1);
                cs[nb][0] += o0; cs[nb][1] += o1;
                cq[nb][0] += o0 * o0; cq[nb][1] += o1 * o1;
            }
            if (v1) {
                *(float2*)(outp + (size_t)r1 * HH + c) = make_float2(o2, o3);
                cs[nb][0] += o2; cs[nb][1] += o3;
                cq[nb][0] += o2 * o2; cq[nb][1] += o3 * o3;
            }
        }
    }
#pragma unroll
    for (int nb = 0; nb < 4; nb++) {
#pragma unroll
        for (int j = 0; j < 2; j++) {
            float s = cs[nb][j], q = cq[nb][j];
#pragma unroll
            for (int off = 16; off >= 4; off >>= 1) {
                s += __shfl_down_sync(0xffffffffu, s, off);
                q += __shfl_down_sync(0xffffffffu, q, off);
            }
            if (lane < 4) {
                int c = wn * 32 + nb * 8 + lane * 2 + j;
                sS[wm * HH + c] = s;
                sQ[wm * HH + c] = q;
            }
        }
    }
    __syncthreads();
    if (tid < HH) {
        float s = sS[tid] + sS[HH + tid];
        float q = sQ[tid] + sQ[HH + tid];
        float* st = g_stats + ((MODE == 1) ? 0 : 2 * HH);
        atomicAdd(st + tid, s);
        atomicAdd(st + HH + tid, q);
    }
}

// pool: BN2 of last layer finalized per-block, scatter to g_pool
__global__ void __launch_bounds__(256)
k_pool(const int* __restrict__ batch,
       const float* __restrict__ bg, const float* __restrict__ bb) {
    __shared__ float s_sc[HH], s_sh[HH];
    const int tid = threadIdx.x;
    if (tid < HH) {
        float mu  = g_stats[2 * HH + tid] * (1.f / (float)NN);
        float msq = g_stats[3 * HH + tid] * (1.f / (float)NN);
        float rstd = rsqrtf(msq - mu * mu + 1e-5f);
        float s = __ldg(bg + tid) * rstd;
        s_sc[tid] = s;
        s_sh[tid] = __ldg(bb + tid) - s * mu;
    }
    __syncthreads();
    const int n = blockIdx.x * 8 + (tid >> 5);
    if (n >= NN) return;
    const int c = (tid & 31) << 2;
    float4 y = *(const float4*)(g_P + (size_t)n * HH + c);
    float4 o;
    o.x = fmaf(s_sc[c + 0], y.x, s_sh[c + 0]);
    o.y = fmaf(s_sc[c + 1], y.y, s_sh[c + 1]);
    o.z = fmaf(s_sc[c + 2], y.z, s_sh[c + 2]);
    o.w = fmaf(s_sc[c + 3], y.w, s_sh[c + 3]);
    red_add_v4(g_pool + (size_t)__ldg(batch + n) * HH + c, o);
}

// k_final v2: cw1 cached in 64KB smem; 32 graphs per block; 256 blocks.
#define FG 32
#define FINAL_SMEM (HH * HH * 4)
__global__ void __launch_bounds__(256)
k_final(const float* __restrict__ cw1, const float* __restrict__ cb1,
        const float* __restrict__ cw2, const float* __restrict__ cb2,
        float* __restrict__ out) {
    extern __shared__ float sm[];           // cw1: 16384 floats
    __shared__ float sp[HH];
    __shared__ float spart[2][HH];
    __shared__ float rb[4];
    const int tid = threadIdx.x;
    for (int i = tid; i < HH * HH / 4; i += 256)
        *(float4*)(sm + i * 4) = *(const float4*)(cw1 + i * 4);
    __syncthreads();
    const int j = tid & 127, half = tid >> 7;
    const int i0 = half * 64;
    for (int g0 = 0; g0 < FG; g0++) {
        int g = blockIdx.x * FG + g0;
        if (tid < HH) sp[tid] = g_pool[(size_t)g * HH + tid];
        __syncthreads();
        float acc = 0.f;
#pragma unroll 8
        for (int i = i0; i < i0 + 64; i++)
            acc = fmaf(sp[i], sm[i * HH + j], acc);
        spart[half][j] = acc;
        __syncthreads();
        if (tid < HH) {
            float v = fmaxf(spart[0][tid] + spart[1][tid] + __ldg(cb1 + tid), 0.f)
                      * __ldg(cw2 + tid);
#pragma unroll
            for (int off = 16; off > 0; off >>= 1)
                v += __shfl_down_sync(0xffffffffu, v, off);
            if ((tid & 31) == 0) rb[tid >> 5] = v;
        }
        __syncthreads();
        if (tid == 0) out[g] = rb[0] + rb[1] + rb[2] + rb[3] + __ldg(cb2);
        __syncthreads();
    }
}

extern "C" void kernel_launch(void* const* d_in, const int* in_sizes, int n_in,
                              void* d_out, int out_size) {
    const int*   x     = (const int*)d_in[0];
    const int*   ei    = (const int*)d_in[1];
    const int*   ea    = (const int*)d_in[2];
    const int*   batch = (const int*)d_in[3];
    const float* aemb  = (const float*)d_in[4];
    const float* bemb  = (const float*)d_in[5];
    const float* eps   = (const float*)d_in[6];
    const float* w1    = (const float*)d_in[7];
    const float* b1    = (const float*)d_in[8];
    const float* bn1g  = (const float*)d_in[9];
    const float* bn1b  = (const float*)d_in[10];
    const float* w2    = (const float*)d_in[11];
    const float* b2    = (const float*)d_in[12];
    const float* bng   = (const float*)d_in[13];
    const float* bnb   = (const float*)d_in[14];
    const float* cw1   = (const float*)d_in[15];
    const float* cb1   = (const float*)d_in[16];
    const float* cw2   = (const float*)d_in[17];
    const float* cb2   = (const float*)d_in[18];
    float* out = (float*)d_out;
    const int* row = ei;
    const int* col = ei + EE;

    cudaFuncSetAttribute(k_mma<1>, cudaFuncAttributeMaxDynamicSharedMemorySize, GEMM_SMEM);
    cudaFuncSetAttribute(k_mma<2>, cudaFuncAttributeMaxDynamicSharedMemorySize, GEMM_SMEM);
    cudaFuncSetAttribute(k_final, cudaFuncAttributeMaxDynamicSharedMemorySize, FINAL_SMEM);

    const int NT = 256;
    const int gridE  = (EE + NT - 1) / NT;
    const int gridGEMM = (NN + 63) / 64;          // 4688
    const int gridNode = (NN + 7) / 8;            // 37500

    k_init<<<2048, NT>>>();
    k_prepw<<<dim3(16, 10), 256>>>(w1, w2);
    k_prepbond<<<dim3(216, 5), HH>>>(bemb);
    k_cnt<<<gridE, NT>>>(row, col);
    k_scan<<<2, 1024>>>();
    k_fill<<<gridE, NT>>>(row, col, ea);
    for (int l = 0; l < 5; l++) {
        if (l == 0)
            k_node<1><<<gridNode, NT>>>(0, nullptr, nullptr, x, aemb);
        else
            k_node<0><<<gridNode, NT>>>(l, bng + (l - 1) * HH, bnb + (l - 1) * HH,
                                        nullptr, nullptr);
        k_mma<1><<<gridGEMM, NT, GEMM_SMEM>>>(2 * l, b1 + l * HH, eps + l, nullptr, nullptr);
        k_mma<2><<<gridGEMM, NT, GEMM_SMEM>>>(2 * l + 1, b2 + l * HH, nullptr,
                                              bn1g + l * HH, bn1b + l * HH);
    }
    k_pool<<<gridNode, NT>>>(batch, bng + 4 * HH, bnb + 4 * HH);
    k_final<<<GG / FG, NT, FINAL_SMEM>>>(cw1, cb1, cw2, cb2, out);
}

// round 15
// speedup vs baseline: 1.0209x; 1.0209x over previous
#include <cuda_runtime.h>
#include <cuda_bf16.h>
#include <cstdint>

#define NN 300000
#define EE 600000
#define HH 128
#define GG 8192

// ---------------- scratch (device globals: allocation-free) ----------------
__device__ float g_P[(size_t)NN * HH];    // prev-layer raw output (y2 pre-BN)
__device__ float g_HIN[(size_t)NN * HH];  // h_in (fp32 — required by Al split term)
__device__ float g_Y1[(size_t)NN * HH];   // y1 (pre-BN1 GEMM1 output)
__device__ float g_pool[(size_t)GG * HH];
__device__ float g_stats[4 * HH];         // [sum1, sumsq1 | sum2, sumsq2]
__device__ __nv_bfloat16 g_Wh[10 * HH * HH];
__device__ __nv_bfloat16 g_Wl[10 * HH * HH];
// CSR by row (payload cidx) for bond sums; CSC by col (payload row) for aggr gather
__device__ int g_cnt[NN],  g_cur[NN],  g_off[NN + 1];
__device__ int g_cnt2[NN], g_cur2[NN], g_off2[NN + 1];
__device__ unsigned int g_pack[EE];    // cidx (bond table index)
__device__ int g_pack2[EE];            // src row
// precombined bond tables: [5][216][128]
__device__ float g_ctab[5 * 216 * HH];

__device__ __forceinline__ void red_add_v4(float* p, float4 v) {
    asm volatile("red.global.add.v4.f32 [%0], {%1,%2,%3,%4};"
                 :: "l"(p), "f"(v.x), "f"(v.y), "f"(v.z), "f"(v.w) : "memory");
}
__device__ __forceinline__ uint32_t smem_u32(const void* p) {
    uint32_t a;
    asm("{ .reg .u64 t; cvta.to.shared.u64 t, %1; cvt.u32.u64 %0, t; }" : "=r"(a) : "l"(p));
    return a;
}
__device__ __forceinline__ void ldsm4(uint32_t* r, uint32_t addr) {
    asm volatile("ldmatrix.sync.aligned.m8n8.x4.shared.b16 {%0,%1,%2,%3}, [%4];"
                 : "=r"(r[0]), "=r"(r[1]), "=r"(r[2]), "=r"(r[3]) : "r"(addr));
}
__device__ __forceinline__ void mma16816(float* d, const uint32_t* a, const uint32_t* b) {
    asm volatile("mma.sync.aligned.m16n8k16.row.col.f32.bf16.bf16.f32 "
                 "{%0,%1,%2,%3}, {%4,%5,%6,%7}, {%8,%9}, {%0,%1,%2,%3};"
                 : "+f"(d[0]), "+f"(d[1]), "+f"(d[2]), "+f"(d[3])
                 : "r"(a[0]), "r"(a[1]), "r"(a[2]), "r"(a[3]), "r"(b[0]), "r"(b[1]));
}

// ---------------- merged setup: prepw + prepbond + cnt ----------------
// blocks [0,160): weight split; [160,700): bond tables; [700,3044): degree counts
__global__ void k_prepall(const float* __restrict__ w1, const float* __restrict__ w2,
                          const float* __restrict__ bemb,
                          const int* __restrict__ row, const int* __restrict__ col) {
    const int bid = blockIdx.x, tid = threadIdx.x;
    if (bid < 160) {
        int q = bid * 256 + tid;          // [0, 40960)
        int l = q >> 12;                  // 0..9
        int r = q & 4095;
        const float* W = (l < 5) ? (w1 + (size_t)l * HH * HH)
                                 : (w2 + (size_t)(l - 5) * HH * HH);
        int slot = (l < 5) ? (2 * l) : (2 * (l - 5) + 1);
        int k = r >> 5, n0 = (r & 31) * 4;
        float4 w = *(const float4*)(W + (size_t)k * HH + n0);
        float wv[4] = {w.x, w.y, w.z, w.w};
#pragma unroll
        for (int j = 0; j < 4; j++) {
            __nv_bfloat16 h = __float2bfloat16(wv[j]);
            size_t o = (size_t)slot * HH * HH + (size_t)(n0 + j) * HH + k;
            g_Wh[o] = h;
            g_Wl[o] = __float2bfloat16(wv[j] - __bfloat162float(h));
        }
    } else if (bid < 700) {
        int idx = (bid - 160) * 256 + tid;   // [0, 138240)
        int l = idx / 27648;
        int rem = idx % 27648;
        int c = rem >> 7, h = rem & 127;
        int a0 = c / 36, a1 = (c / 6) % 6, a2 = c % 6;
        const float* b = bemb + (size_t)l * 3 * 8 * HH;
        g_ctab[((size_t)l * 216 + c) * HH + h] =
            b[(size_t)(0 * 8 + a0) * HH + h] + b[(size_t)(1 * 8 + a1) * HH + h]
            + b[(size_t)(2 * 8 + a2) * HH + h];
    } else {
        int e = (bid - 700) * 256 + tid;
        if (e < EE) {
            atomicAdd(&g_cnt[__ldg(row + e)], 1);
            atomicAdd(&g_cnt2[__ldg(col + e)], 1);
        }
    }
}

// exclusive scan: block 0 -> (cnt,off), block 1 -> (cnt2,off2)
__global__ void k_scan() {
    __shared__ int bs[1024];
    const int* cnt = (blockIdx.x == 0) ? g_cnt : g_cnt2;
    int* off = (blockIdx.x == 0) ? g_off : g_off2;
    const int t = threadIdx.x;
    const int C = (NN + 1023) / 1024;   // 293
    int base = t * C;
    int s = 0;
    for (int i = 0; i < C; i++) {
        int idx = base + i;
        if (idx < NN) s += cnt[idx];
    }
    bs[t] = s;
    __syncthreads();
    for (int o = 1; o < 1024; o <<= 1) {
        int u = (t >= o) ? bs[t - o] : 0;
        __syncthreads();
        bs[t] += u;
        __syncthreads();
    }
    int run = bs[t] - s;
    for (int i = 0; i < C; i++) {
        int idx = base + i;
        if (idx < NN) { off[idx] = run; run += cnt[idx]; }
    }
    if (t == 1023) off[NN] = EE;
}

__global__ void k_fill(const int* __restrict__ row, const int* __restrict__ col,
                       const int* __restrict__ eattr) {
    int e = blockIdx.x * blockDim.x + threadIdx.x;
    if (e >= EE) return;
    int r = __ldg(row + e);
    int c = __ldg(col + e);
    int a0 = __ldg(eattr + e * 3 + 0);
    int a1 = __ldg(eattr + e * 3 + 1);
    int a2 = __ldg(eattr + e * 3 + 2);
    int pos = g_off[r] + atomicAdd(&g_cur[r], 1);
    g_pack[pos] = (unsigned int)(a0 * 36 + a1 * 6 + a2);
    int pos2 = g_off2[c] + atomicAdd(&g_cur2[c], 1);
    g_pack2[pos2] = r;
}

// ---------------- node kernel (bond sum + act(prev) + hin) ----------------
template<int FIRST>
__global__ void __launch_bounds__(256)
k_node(int layer, const float* __restrict__ bg, const float* __restrict__ bb,
       const int* __restrict__ x, const float* __restrict__ aemb) {
    __shared__ float s_sc[HH], s_sh[HH];
    const int tid = threadIdx.x;
    if (blockIdx.x == 0 && tid < 2 * HH) g_stats[tid] = 0.f;   // zero slot0
    if (!FIRST) {
        if (tid < HH) {
            float mu  = g_stats[2 * HH + tid] * (1.f / (float)NN);
            float msq = g_stats[3 * HH + tid] * (1.f / (float)NN);
            float rstd = rsqrtf(msq - mu * mu + 1e-5f);
            float s = __ldg(bg + tid) * rstd;
            s_sc[tid] = s;
            s_sh[tid] = __ldg(bb + tid) - s * mu;
        }
        __syncthreads();
    }
    const int n = blockIdx.x * 8 + (tid >> 5);
    if (n >= NN) return;
    const int c4 = (tid & 31) << 2;
    const float* ctab = g_ctab + (size_t)layer * 216 * HH;
    const int e0 = __ldg(&g_off[n]), e1 = __ldg(&g_off[n + 1]);
    const float inv = 1.f / ((float)(e1 - e0) + 1.f);

    float4 bsum = make_float4(0.f, 0.f, 0.f, 0.f);
    for (int e = e0; e < e1; e++) {
        unsigned int ci = __ldg(&g_pack[e]);
        const float4 t = *(const float4*)(ctab + (size_t)ci * HH + c4);
        bsum.x += t.x; bsum.y += t.y; bsum.z += t.z; bsum.w += t.w;
    }
    float4 p;
    if (FIRST) {
        p = make_float4(0.f, 0.f, 0.f, 0.f);
#pragma unroll
        for (int f = 0; f < 9; f++) {
            int xi = __ldg(x + n * 9 + f);
            const float4 e = *(const float4*)(aemb + ((size_t)(f * 128 + xi) * HH + c4));
            p.x += e.x; p.y += e.y; p.z += e.z; p.w += e.w;
        }
    } else {
        p = *(const float4*)(g_P + (size_t)n * HH + c4);
        p.x = fmaxf(fmaf(s_sc[c4 + 0], p.x, s_sh[c4 + 0]), 0.f);
        p.y = fmaxf(fmaf(s_sc[c4 + 1], p.y, s_sh[c4 + 1]), 0.f);
        p.z = fmaxf(fmaf(s_sc[c4 + 2], p.z, s_sh[c4 + 2]), 0.f);
        p.w = fmaxf(fmaf(s_sc[c4 + 3], p.w, s_sh[c4 + 3]), 0.f);
    }
    float4 h;
    h.x = fmaf(bsum.x, inv, p.x);
    h.y = fmaf(bsum.y, inv, p.y);
    h.z = fmaf(bsum.z, inv, p.z);
    h.w = fmaf(bsum.w, inv, p.w);
    *(float4*)(g_HIN + (size_t)n * HH + c4) = h;
}

// ---------------- HMMA bf16-split GEMM, M-tile 64, two-pass B, 3 CTAs/SM ----
// pass1: B=Wh, acc += Ah*B + Al*B;  pass2: B=Wl, acc += Ah*B.  (R10 structure)
#define PAD 136
#define GEMM_SMEM 71680

template<int MODE>
__global__ void __launch_bounds__(256, 3)
k_mma(int wslot, const float* __restrict__ bias,
      const float* __restrict__ epsp,
      const float* __restrict__ bg, const float* __restrict__ bb) {
    extern __shared__ char dsm[];
    __shared__ float s_sc[HH], s_sh[HH];

    const uint32_t su = smem_u32(dsm);
    const uint32_t Ah_u = su, Al_u = su + 17408;
    const uint32_t B_u = su + 34816;
    __nv_bfloat16* Ah = (__nv_bfloat16*)dsm;
    __nv_bfloat16* Al = (__nv_bfloat16*)(dsm + 17408);
    __nv_bfloat16* Bs = (__nv_bfloat16*)(dsm + 34816);
    float* sS = (float*)(dsm + 69632);   // [2][128]
    float* sQ = (float*)(dsm + 70656);   // [2][128]

    const int tid = threadIdx.x;
    const int wid = tid >> 5, lane = tid & 31;
    const int wm = wid & 1, wn = wid >> 1;
    const int m0 = blockIdx.x * 64;

    if (MODE == 1 && blockIdx.x == 0 && tid < 2 * HH)
        g_stats[2 * HH + tid] = 0.f;   // zero slot1 for upcoming GEMM2
    if (MODE == 2 && tid < HH) {
        float mu  = g_stats[tid] * (1.f / (float)NN);
        float msq = g_stats[HH + tid] * (1.f / (float)NN);
        float rstd = rsqrtf(msq - mu * mu + 1e-5f);
        float s = __ldg(bg + tid) * rstd;
        s_sc[tid] = s;
        s_sh[tid] = __ldg(bb + tid) - s * mu;
    }
    const float epsl = (MODE == 1) ? (1.f + __ldg(epsp)) : 0.f;
    if (MODE == 2) __syncthreads();

    // ---- pass-1 W tile: hi ----
    const __nv_bfloat16* wh = g_Wh + (size_t)wslot * HH * HH;
    const __nv_bfloat16* wl = g_Wl + (size_t)wslot * HH * HH;
#pragma unroll
    for (int it = 0; it < 8; it++) {
        int q = it * 256 + tid;
        int n = q >> 4, k0 = (q & 15) * 8;
        *(uint4*)(Bs + n * PAD + k0) = *(const uint4*)(wh + n * HH + k0);
    }

    // ---- A: load + transform + split ----
    const int w = tid >> 5;
    const int c0 = (tid & 31) * 4;
    if (MODE == 1) {
        // two groups of 4 rows; within a group all loads are independent (MLP)
#pragma unroll
        for (int g = 0; g < 2; g++) {
            int rg[4], ea[4], eb[4];
#pragma unroll
            for (int i = 0; i < 4; i++) {
                rg[i] = m0 + (g * 4 + i) * 8 + w;
                bool ok = rg[i] < NN;
                ea[i] = ok ? __ldg(&g_off2[rg[i]]) : 0;
                eb[i] = ok ? __ldg(&g_off2[rg[i] + 1]) : 0;
            }
            int src[4][4];
#pragma unroll
            for (int i = 0; i < 4; i++) {
                int d = eb[i] - ea[i];
#pragma unroll
                for (int j = 0; j < 4; j++) {
                    int idx = ea[i] + ((j < d) ? j : 0);
                    src[i][j] = (d > 0) ? __ldg(&g_pack2[idx]) : 0;
                }
            }
            float4 vv[4];
#pragma unroll
            for (int i = 0; i < 4; i++) {
                float4 v = make_float4(0.f, 0.f, 0.f, 0.f);
                if (rg[i] < NN) {
                    float4 hv = *(const float4*)(g_HIN + (size_t)rg[i] * HH + c0);
                    v.x = epsl * hv.x; v.y = epsl * hv.y;
                    v.z = epsl * hv.z; v.w = epsl * hv.w;
                }
                vv[i] = v;
            }
#pragma unroll
            for (int j = 0; j < 4; j++) {
#pragma unroll
                for (int i = 0; i < 4; i++) {
                    if (j < eb[i] - ea[i]) {
                        float4 a = *(const float4*)(g_HIN + (size_t)src[i][j] * HH + c0);
                        vv[i].x += a.x; vv[i].y += a.y;
                        vv[i].z += a.z; vv[i].w += a.w;
                    }
                }
            }
#pragma unroll
            for (int i = 0; i < 4; i++) {
                for (int e = ea[i] + 4; e < eb[i]; e++) {
                    int s0 = __ldg(&g_pack2[e]);
                    float4 a = *(const float4*)(g_HIN + (size_t)s0 * HH + c0);
                    vv[i].x += a.x; vv[i].y += a.y;
                    vv[i].z += a.z; vv[i].w += a.w;
                }
            }
#pragma unroll
            for (int i = 0; i < 4; i++) {
                int r = (g * 4 + i) * 8 + w;
                float fv[4] = {vv[i].x, vv[i].y, vv[i].z, vv[i].w};
                __nv_bfloat16 hb[4], lb[4];
#pragma unroll
                for (int j = 0; j < 4; j++) {
                    hb[j] = __float2bfloat16(fv[j]);
                    lb[j] = __float2bfloat16(fv[j] - __bfloat162float(hb[j]));
                }
                *(uint2*)(Ah + r * PAD + c0) = *(uint2*)hb;
                *(uint2*)(Al + r * PAD + c0) = *(uint2*)lb;
            }
        }
    } else {
#pragma unroll
        for (int it = 0; it < 8; it++) {
            int r = it * 8 + w;
            int grow = m0 + r;
            float4 v = make_float4(0.f, 0.f, 0.f, 0.f);
            if (grow < NN) {
                float4 y = *(const float4*)(g_Y1 + (size_t)grow * HH + c0);
                v.x = fmaxf(fmaf(s_sc[c0 + 0], y.x, s_sh[c0 + 0]), 0.f);
                v.y = fmaxf(fmaf(s_sc[c0 + 1], y.y, s_sh[c0 + 1]), 0.f);
                v.z = fmaxf(fmaf(s_sc[c0 + 2], y.z, s_sh[c0 + 2]), 0.f);
                v.w = fmaxf(fmaf(s_sc[c0 + 3], y.w, s_sh[c0 + 3]), 0.f);
            }
            float fv[4] = {v.x, v.y, v.z, v.w};
            __nv_bfloat16 hb[4], lb[4];
#pragma unroll
            for (int j = 0; j < 4; j++) {
                hb[j] = __float2bfloat16(fv[j]);
                lb[j] = __float2bfloat16(fv[j] - __bfloat162float(hb[j]));
            }
            *(uint2*)(Ah + r * PAD + c0) = *(uint2*)hb;
            *(uint2*)(Al + r * PAD + c0) = *(uint2*)lb;
        }
    }
    __syncthreads();

    float acc[2][4][4];
#pragma unroll
    for (int mi = 0; mi < 2; mi++)
#pragma unroll
        for (int nb = 0; nb < 4; nb++)
#pragma unroll
            for (int j = 0; j < 4; j++) acc[mi][nb][j] = 0.f;

    const int aRow = wm * 32 + (lane & 15);
    const int aKs = (lane >> 4) * 8;
    const int bN = wn * 32 + (lane >> 4) * 8 + (lane & 7);
    const int bKs = ((lane >> 3) & 1) * 8;

    // ---- pass 1: acc += Ah*Bh + Al*Bh ----
#pragma unroll
    for (int ks = 0; ks < 8; ks++) {
        uint32_t ah[2][4], al[2][4], bbq[2][4];
#pragma unroll
        for (int mi = 0; mi < 2; mi++) {
            uint32_t ra = (uint32_t)(((aRow + mi * 16) * PAD + ks * 16 + aKs) * 2);
            ldsm4(ah[mi], Ah_u + ra);
            ldsm4(al[mi], Al_u + ra);
        }
#pragma unroll
        for (int nb2 = 0; nb2 < 2; nb2++) {
            uint32_t rb = (uint32_t)(((bN + nb2 * 16) * PAD + ks * 16 + bKs) * 2);
            ldsm4(bbq[nb2], B_u + rb);
        }
#pragma unroll
        for (int mi = 0; mi < 2; mi++)
#pragma unroll
            for (int nb = 0; nb < 4; nb++) {
                const uint32_t* bp = &bbq[nb >> 1][(nb & 1) * 2];
                mma16816(acc[mi][nb], ah[mi], bp);
                mma16816(acc[mi][nb], al[mi], bp);
            }
    }
    __syncthreads();   // all warps done reading Bh

    // ---- pass-2 W tile: lo ----
#pragma unroll
    for (int it = 0; it < 8; it++) {
        int q = it * 256 + tid;
        int n = q >> 4, k0 = (q & 15) * 8;
        *(uint4*)(Bs + n * PAD + k0) = *(const uint4*)(wl + n * HH + k0);
    }
    __syncthreads();

    // ---- pass 2: acc += Ah*Bl ----
#pragma unroll
    for (int ks = 0; ks < 8; ks++) {
        uint32_t ah[2][4], bbq[2][4];
#pragma unroll
        for (int mi = 0; mi < 2; mi++) {
            uint32_t ra = (uint32_t)(((aRow + mi * 16) * PAD + ks * 16 + aKs) * 2);
            ldsm4(ah[mi], Ah_u + ra);
        }
#pragma unroll
        for (int nb2 = 0; nb2 < 2; nb2++) {
            uint32_t rb = (uint32_t)(((bN + nb2 * 16) * PAD + ks * 16 + bKs) * 2);
            ldsm4(bbq[nb2], B_u + rb);
        }
#pragma unroll
        for (int mi = 0; mi < 2; mi++)
#pragma unroll
            for (int nb = 0; nb < 4; nb++)
                mma16816(acc[mi][nb], ah[mi], &bbq[nb >> 1][(nb & 1) * 2]);
    }

    // ---- epilogue: bias, store, per-column stats ----
    float* outp = (MODE == 1) ? g_Y1 : g_P;
    float cs[4][2], cq[4][2];
#pragma unroll
    for (int nb = 0; nb < 4; nb++) { cs[nb][0] = cs[nb][1] = 0.f; cq[nb][0] = cq[nb][1] = 0.f; }
    float bse[4][2];
#pragma unroll
    for (int nb = 0; nb < 4; nb++) {
        int c = wn * 32 + nb * 8 + (lane & 3) * 2;
        bse[nb][0] = __ldg(bias + c);
        bse[nb][1] = __ldg(bias + c + 1);
    }
#pragma unroll
    for (int mi = 0; mi < 2; mi++) {
        int r0 = m0 + wm * 32 + mi * 16 + (lane >> 2);
        int r1 = r0 + 8;
        bool v0 = r0 < NN, v1 = r1 < NN;
#pragma unroll
        for (int nb = 0; nb < 4; nb++) {
            int c = wn * 32 + nb * 8 + (lane & 3) * 2;
            float o0 = acc[mi][nb][0] + bse[nb][0];
            float o1 = acc[mi][nb][1] + bse[nb][1];
            float o2 = acc[mi][nb][2] + bse[nb][0];
            float o3 = acc[mi][nb][3] + bse[nb][1];
            if (v0) {
                *(float2*)(outp + (size_t)r0 * HH + c) = make_float2(o0, o1);
                cs[nb][0] += o0; cs[nb][1] += o1;
                cq[nb][0] += o0 * o0; cq[nb][1] += o1 * o1;
            }
            if (v1) {
                *(float2*)(outp + (size_t)r1 * HH + c) = make_float2(o2, o3);
                cs[nb][0] += o2; cs[nb][1] += o3;
                cq[nb][0] += o2 * o2; cq[nb][1] += o3 * o3;
            }
        }
    }
#pragma unroll
    for (int nb = 0; nb < 4; nb++) {
#pragma unroll
        for (int j = 0; j < 2; j++) {
            float s = cs[nb][j], q = cq[nb][j];
#pragma unroll
            for (int off = 16; off >= 4; off >>= 1) {
                s += __shfl_down_sync(0xffffffffu, s, off);
                q += __shfl_down_sync(0xffffffffu, q, off);
            }
            if (lane < 4) {
                int c = wn * 32 + nb * 8 + lane * 2 + j;
                sS[wm * HH + c] = s;
                sQ[wm * HH + c] = q;
            }
        }
    }
    __syncthreads();
    if (tid < HH) {
        float s = sS[tid] + sS[HH + tid];
        float q = sQ[tid] + sQ[HH + tid];
        float* st = g_stats + ((MODE == 1) ? 0 : 2 * HH);
        atomicAdd(st + tid, s);
        atomicAdd(st + HH + tid, q);
    }
}

// pool: BN2 of last layer finalized per-block, scatter to g_pool
__global__ void __launch_bounds__(256)
k_pool(const int* __restrict__ batch,
       const float* __restrict__ bg, const float* __restrict__ bb) {
    __shared__ float s_sc[HH], s_sh[HH];
    const int tid = threadIdx.x;
    if (tid < HH) {
        float mu  = g_stats[2 * HH + tid] * (1.f / (float)NN);
        float msq = g_stats[3 * HH + tid] * (1.f / (float)NN);
        float rstd = rsqrtf(msq - mu * mu + 1e-5f);
        float s = __ldg(bg + tid) * rstd;
        s_sc[tid] = s;
        s_sh[tid] = __ldg(bb + tid) - s * mu;
    }
    __syncthreads();
    const int n = blockIdx.x * 8 + (tid >> 5);
    if (n >= NN) return;
    const int c = (tid & 31) << 2;
    float4 y = *(const float4*)(g_P + (size_t)n * HH + c);
    float4 o;
    o.x = fmaf(s_sc[c + 0], y.x, s_sh[c + 0]);
    o.y = fmaf(s_sc[c + 1], y.y, s_sh[c + 1]);
    o.z = fmaf(s_sc[c + 2], y.z, s_sh[c + 2]);
    o.w = fmaf(s_sc[c + 3], y.w, s_sh[c + 3]);
    red_add_v4(g_pool + (size_t)__ldg(batch + n) * HH + c, o);
}

__global__ void k_final(const float* __restrict__ cw1, const float* __restrict__ cb1,
                        const float* __restrict__ cw2, const float* __restrict__ cb2,
                        float* __restrict__ out) {
    __shared__ float p[HH];
    __shared__ float rb[4];
    int j = threadIdx.x;
    p[j] = g_pool[(size_t)blockIdx.x * HH + j];
    __syncthreads();
    float acc = __ldg(cb1 + j);
#pragma unroll 8
    for (int i = 0; i < HH; i++)
        acc = fmaf(p[i], __ldg(cw1 + i * HH + j), acc);
    float v = fmaxf(acc, 0.f) * __ldg(cw2 + j);
#pragma unroll
    for (int off = 16; off > 0; off >>= 1)
        v += __shfl_down_sync(0xffffffffu, v, off);
    if ((j & 31) == 0) rb[j >> 5] = v;
    __syncthreads();
    if (j == 0) out[blockIdx.x] = rb[0] + rb[1] + rb[2] + rb[3] + __ldg(cb2);
}

extern "C" void kernel_launch(void* const* d_in, const int* in_sizes, int n_in,
                              void* d_out, int out_size) {
    const int*   x     = (const int*)d_in[0];
    const int*   ei    = (const int*)d_in[1];
    const int*   ea    = (const int*)d_in[2];
    const int*   batch = (const int*)d_in[3];
    const float* aemb  = (const float*)d_in[4];
    const float* bemb  = (const float*)d_in[5];
    const float* eps   = (const float*)d_in[6];
    const float* w1    = (const float*)d_in[7];
    const float* b1    = (const float*)d_in[8];
    const float* bn1g  = (const float*)d_in[9];
    const float* bn1b  = (const float*)d_in[10];
    const float* w2    = (const float*)d_in[11];
    const float* b2    = (const float*)d_in[12];
    const float* bng   = (const float*)d_in[13];
    const float* bnb   = (const float*)d_in[14];
    const float* cw1   = (const float*)d_in[15];
    const float* cb1   = (const float*)d_in[16];
    const float* cw2   = (const float*)d_in[17];
    const float* cb2   = (const float*)d_in[18];
    float* out = (float*)d_out;
    const int* row = ei;
    const int* col = ei + EE;

    cudaFuncSetAttribute(k_mma<1>, cudaFuncAttributeMaxDynamicSharedMemorySize, GEMM_SMEM);
    cudaFuncSetAttribute(k_mma<2>, cudaFuncAttributeMaxDynamicSharedMemorySize, GEMM_SMEM);

    // zero counters/pool via async memsets (graph-capturable; no allocation)
    void *p_cnt, *p_cur, *p_cnt2, *p_cur2, *p_pool;
    cudaGetSymbolAddress(&p_cnt, g_cnt);
    cudaGetSymbolAddress(&p_cur, g_cur);
    cudaGetSymbolAddress(&p_cnt2, g_cnt2);
    cudaGetSymbolAddress(&p_cur2, g_cur2);
    cudaGetSymbolAddress(&p_pool, g_pool);
    cudaMemsetAsync(p_cnt, 0, NN * sizeof(int));
    cudaMemsetAsync(p_cur, 0, NN * sizeof(int));
    cudaMemsetAsync(p_cnt2, 0, NN * sizeof(int));
    cudaMemsetAsync(p_cur2, 0, NN * sizeof(int));
    cudaMemsetAsync(p_pool, 0, (size_t)GG * HH * sizeof(float));

    const int NT = 256;
    const int gridE  = (EE + NT - 1) / NT;        // 2344
    const int gridGEMM = (NN + 63) / 64;          // 4688
    const int gridNode = (NN + 7) / 8;            // 37500

    k_prepall<<<3044, NT>>>(w1, w2, bemb, row, col);   // launch 0
    k_scan<<<2, 1024>>>();                             // launch 1
    k_fill<<<gridE, NT>>>(row, col, ea);               // launch 2
    for (int l = 0; l < 5; l++) {
        if (l == 0)
            k_node<1><<<gridNode, NT>>>(0, nullptr, nullptr, x, aemb);  // launch 3: profiled
        else
            k_node<0><<<gridNode, NT>>>(l, bng + (l - 1) * HH, bnb + (l - 1) * HH,
                                        nullptr, nullptr);
        k_mma<1><<<gridGEMM, NT, GEMM_SMEM>>>(2 * l, b1 + l * HH, eps + l, nullptr, nullptr);
        k_mma<2><<<gridGEMM, NT, GEMM_SMEM>>>(2 * l + 1, b2 + l * HH, nullptr,
                                              bn1g + l * HH, bn1b + l * HH);
    }
    k_pool<<<gridNode, NT>>>(batch, bng + 4 * HH, bnb + 4 * HH);
    k_final<<<GG, HH>>>(cw1, cb1, cw2, cb2, out);
}

// round 16
// speedup vs baseline: 1.0469x; 1.0255x over previous
#include <cuda_runtime.h>
#include <cuda_bf16.h>
#include <cstdint>

#define NN 300000
#define EE 600000
#define HH 128
#define GG 8192

// ---------------- scratch (device globals: allocation-free) ----------------
__device__ float g_P[(size_t)NN * HH];    // prev-layer raw output (y2 pre-BN)
__device__ float g_HIN[(size_t)NN * HH];  // h_in (fp32 — required by Al split term)
__device__ float g_Y1[(size_t)NN * HH];   // y1 (pre-BN1 GEMM1 output)
__device__ float g_pool[(size_t)GG * HH];
__device__ float g_stats[4 * HH];         // [sum1, sumsq1 | sum2, sumsq2]
__device__ __nv_bfloat16 g_Wh[10 * HH * HH];
__device__ __nv_bfloat16 g_Wl[10 * HH * HH];
// CSR by row (payload cidx) for bond sums; CSC by col (payload row) for aggr gather
__device__ int g_cnt[NN],  g_cur[NN],  g_off[NN + 1];
__device__ int g_cnt2[NN], g_cur2[NN], g_off2[NN + 1];
__device__ unsigned int g_pack[EE];    // cidx (bond table index)
__device__ int g_pack2[EE];            // src row
// precombined bond tables: [5][216][128]
__device__ float g_ctab[5 * 216 * HH];

__device__ __forceinline__ void red_add_v4(float* p, float4 v) {
    asm volatile("red.global.add.v4.f32 [%0], {%1,%2,%3,%4};"
                 :: "l"(p), "f"(v.x), "f"(v.y), "f"(v.z), "f"(v.w) : "memory");
}
__device__ __forceinline__ uint32_t smem_u32(const void* p) {
    uint32_t a;
    asm("{ .reg .u64 t; cvta.to.shared.u64 t, %1; cvt.u32.u64 %0, t; }" : "=r"(a) : "l"(p));
    return a;
}
__device__ __forceinline__ void ldsm4(uint32_t* r, uint32_t addr) {
    asm volatile("ldmatrix.sync.aligned.m8n8.x4.shared.b16 {%0,%1,%2,%3}, [%4];"
                 : "=r"(r[0]), "=r"(r[1]), "=r"(r[2]), "=r"(r[3]) : "r"(addr));
}
__device__ __forceinline__ void mma16816(float* d, const uint32_t* a, const uint32_t* b) {
    asm volatile("mma.sync.aligned.m16n8k16.row.col.f32.bf16.bf16.f32 "
                 "{%0,%1,%2,%3}, {%4,%5,%6,%7}, {%8,%9}, {%0,%1,%2,%3};"
                 : "+f"(d[0]), "+f"(d[1]), "+f"(d[2]), "+f"(d[3])
                 : "r"(a[0]), "r"(a[1]), "r"(a[2]), "r"(a[3]), "r"(b[0]), "r"(b[1]));
}

// ---------------- merged setup: prepw + prepbond + cnt ----------------
// blocks [0,160): weight split; [160,700): bond tables; [700,3044): degree counts
__global__ void k_prepall(const float* __restrict__ w1, const float* __restrict__ w2,
                          const float* __restrict__ bemb,
                          const int* __restrict__ row, const int* __restrict__ col) {
    const int bid = blockIdx.x, tid = threadIdx.x;
    if (bid < 160) {
        int q = bid * 256 + tid;          // [0, 40960)
        int l = q >> 12;                  // 0..9
        int r = q & 4095;
        const float* W = (l < 5) ? (w1 + (size_t)l * HH * HH)
                                 : (w2 + (size_t)(l - 5) * HH * HH);
        int slot = (l < 5) ? (2 * l) : (2 * (l - 5) + 1);
        int k = r >> 5, n0 = (r & 31) * 4;
        float4 w = *(const float4*)(W + (size_t)k * HH + n0);
        float wv[4] = {w.x, w.y, w.z, w.w};
#pragma unroll
        for (int j = 0; j < 4; j++) {
            __nv_bfloat16 h = __float2bfloat16(wv[j]);
            size_t o = (size_t)slot * HH * HH + (size_t)(n0 + j) * HH + k;
            g_Wh[o] = h;
            g_Wl[o] = __float2bfloat16(wv[j] - __bfloat162float(h));
        }
    } else if (bid < 700) {
        int idx = (bid - 160) * 256 + tid;   // [0, 138240)
        int l = idx / 27648;
        int rem = idx % 27648;
        int c = rem >> 7, h = rem & 127;
        int a0 = c / 36, a1 = (c / 6) % 6, a2 = c % 6;
        const float* b = bemb + (size_t)l * 3 * 8 * HH;
        g_ctab[((size_t)l * 216 + c) * HH + h] =
            b[(size_t)(0 * 8 + a0) * HH + h] + b[(size_t)(1 * 8 + a1) * HH + h]
            + b[(size_t)(2 * 8 + a2) * HH + h];
    } else {
        int e = (bid - 700) * 256 + tid;
        if (e < EE) {
            atomicAdd(&g_cnt[__ldg(row + e)], 1);
            atomicAdd(&g_cnt2[__ldg(col + e)], 1);
        }
    }
}

// exclusive scan: block 0 -> (cnt,off), block 1 -> (cnt2,off2)
__global__ void k_scan() {
    __shared__ int bs[1024];
    const int* cnt = (blockIdx.x == 0) ? g_cnt : g_cnt2;
    int* off = (blockIdx.x == 0) ? g_off : g_off2;
    const int t = threadIdx.x;
    const int C = (NN + 1023) / 1024;   // 293
    int base = t * C;
    int s = 0;
    for (int i = 0; i < C; i++) {
        int idx = base + i;
        if (idx < NN) s += cnt[idx];
    }
    bs[t] = s;
    __syncthreads();
    for (int o = 1; o < 1024; o <<= 1) {
        int u = (t >= o) ? bs[t - o] : 0;
        __syncthreads();
        bs[t] += u;
        __syncthreads();
    }
    int run = bs[t] - s;
    for (int i = 0; i < C; i++) {
        int idx = base + i;
        if (idx < NN) { off[idx] = run; run += cnt[idx]; }
    }
    if (t == 1023) off[NN] = EE;
}

__global__ void k_fill(const int* __restrict__ row, const int* __restrict__ col,
                       const int* __restrict__ eattr) {
    int e = blockIdx.x * blockDim.x + threadIdx.x;
    if (e >= EE) return;
    int r = __ldg(row + e);
    int c = __ldg(col + e);
    int a0 = __ldg(eattr + e * 3 + 0);
    int a1 = __ldg(eattr + e * 3 + 1);
    int a2 = __ldg(eattr + e * 3 + 2);
    int pos = g_off[r] + atomicAdd(&g_cur[r], 1);
    g_pack[pos] = (unsigned int)(a0 * 36 + a1 * 6 + a2);
    int pos2 = g_off2[c] + atomicAdd(&g_cur2[c], 1);
    g_pack2[pos2] = r;
}

// ---------------- node kernel (bond sum + act(prev) + hin) ----------------
// Independent prev-activation chain hoisted ABOVE the bond loop so both
// memory chains overlap (profile: k_node latency-bound, issue 39%).
template<int FIRST>
__global__ void __launch_bounds__(256)
k_node(int layer, const float* __restrict__ bg, const float* __restrict__ bb,
       const int* __restrict__ x, const float* __restrict__ aemb) {
    __shared__ float s_sc[HH], s_sh[HH];
    const int tid = threadIdx.x;
    if (blockIdx.x == 0 && tid < 2 * HH) g_stats[tid] = 0.f;   // zero slot0
    if (!FIRST) {
        if (tid < HH) {
            float mu  = g_stats[2 * HH + tid] * (1.f / (float)NN);
            float msq = g_stats[3 * HH + tid] * (1.f / (float)NN);
            float rstd = rsqrtf(msq - mu * mu + 1e-5f);
            float s = __ldg(bg + tid) * rstd;
            s_sc[tid] = s;
            s_sh[tid] = __ldg(bb + tid) - s * mu;
        }
        __syncthreads();
    }
    const int n = blockIdx.x * 8 + (tid >> 5);
    if (n >= NN) return;
    const int c4 = (tid & 31) << 2;
    const float* ctab = g_ctab + (size_t)layer * 216 * HH;
    const int e0 = __ldg(&g_off[n]), e1 = __ldg(&g_off[n + 1]);
    const float inv = 1.f / ((float)(e1 - e0) + 1.f);

    // ---- prev-activation chain FIRST (independent of bond loop) ----
    float4 p;
    if (FIRST) {
        p = make_float4(0.f, 0.f, 0.f, 0.f);
#pragma unroll
        for (int f = 0; f < 9; f++) {
            int xi = __ldg(x + n * 9 + f);
            const float4 e = *(const float4*)(aemb + ((size_t)(f * 128 + xi) * HH + c4));
            p.x += e.x; p.y += e.y; p.z += e.z; p.w += e.w;
        }
    } else {
        p = *(const float4*)(g_P + (size_t)n * HH + c4);   // raw load issued early
    }

    // ---- bond gather loop (overlaps with p's chain in flight) ----
    float4 bsum = make_float4(0.f, 0.f, 0.f, 0.f);
    for (int e = e0; e < e1; e++) {
        unsigned int ci = __ldg(&g_pack[e]);
        const float4 t = *(const float4*)(ctab + (size_t)ci * HH + c4);
        bsum.x += t.x; bsum.y += t.y; bsum.z += t.z; bsum.w += t.w;
    }

    if (!FIRST) {
        p.x = fmaxf(fmaf(s_sc[c4 + 0], p.x, s_sh[c4 + 0]), 0.f);
        p.y = fmaxf(fmaf(s_sc[c4 + 1], p.y, s_sh[c4 + 1]), 0.f);
        p.z = fmaxf(fmaf(s_sc[c4 + 2], p.z, s_sh[c4 + 2]), 0.f);
        p.w = fmaxf(fmaf(s_sc[c4 + 3], p.w, s_sh[c4 + 3]), 0.f);
    }
    float4 h;
    h.x = fmaf(bsum.x, inv, p.x);
    h.y = fmaf(bsum.y, inv, p.y);
    h.z = fmaf(bsum.z, inv, p.z);
    h.w = fmaf(bsum.w, inv, p.w);
    *(float4*)(g_HIN + (size_t)n * HH + c4) = h;
}

// ---------------- HMMA bf16-split GEMM, M-tile 64, two-pass B, 3 CTAs/SM ----
// pass1: B=Wh, acc += Ah*B + Al*B;  pass2: B=Wl, acc += Ah*B.  (R10 structure)
#define PAD 136
#define GEMM_SMEM 71680

template<int MODE>
__global__ void __launch_bounds__(256, 3)
k_mma(int wslot, const float* __restrict__ bias,
      const float* __restrict__ epsp,
      const float* __restrict__ bg, const float* __restrict__ bb) {
    extern __shared__ char dsm[];
    __shared__ float s_sc[HH], s_sh[HH];

    const uint32_t su = smem_u32(dsm);
    const uint32_t Ah_u = su, Al_u = su + 17408;
    const uint32_t B_u = su + 34816;
    __nv_bfloat16* Ah = (__nv_bfloat16*)dsm;
    __nv_bfloat16* Al = (__nv_bfloat16*)(dsm + 17408);
    __nv_bfloat16* Bs = (__nv_bfloat16*)(dsm + 34816);
    float* sS = (float*)(dsm + 69632);   // [2][128]
    float* sQ = (float*)(dsm + 70656);   // [2][128]

    const int tid = threadIdx.x;
    const int wid = tid >> 5, lane = tid & 31;
    const int wm = wid & 1, wn = wid >> 1;
    const int m0 = blockIdx.x * 64;

    if (MODE == 1 && blockIdx.x == 0 && tid < 2 * HH)
        g_stats[2 * HH + tid] = 0.f;   // zero slot1 for upcoming GEMM2
    if (MODE == 2 && tid < HH) {
        float mu  = g_stats[tid] * (1.f / (float)NN);
        float msq = g_stats[HH + tid] * (1.f / (float)NN);
        float rstd = rsqrtf(msq - mu * mu + 1e-5f);
        float s = __ldg(bg + tid) * rstd;
        s_sc[tid] = s;
        s_sh[tid] = __ldg(bb + tid) - s * mu;
    }
    const float epsl = (MODE == 1) ? (1.f + __ldg(epsp)) : 0.f;
    if (MODE == 2) __syncthreads();

    // ---- pass-1 W tile: hi ----
    const __nv_bfloat16* wh = g_Wh + (size_t)wslot * HH * HH;
    const __nv_bfloat16* wl = g_Wl + (size_t)wslot * HH * HH;
#pragma unroll
    for (int it = 0; it < 8; it++) {
        int q = it * 256 + tid;
        int n = q >> 4, k0 = (q & 15) * 8;
        *(uint4*)(Bs + n * PAD + k0) = *(const uint4*)(wh + n * HH + k0);
    }

    // ---- A: load + transform + split ----
    const int w = tid >> 5;
    const int c0 = (tid & 31) * 4;
    if (MODE == 1) {
        // two groups of 4 rows; within a group all loads are independent (MLP)
#pragma unroll
        for (int g = 0; g < 2; g++) {
            int rg[4], ea[4], eb[4];
#pragma unroll
            for (int i = 0; i < 4; i++) {
                rg[i] = m0 + (g * 4 + i) * 8 + w;
                bool ok = rg[i] < NN;
                ea[i] = ok ? __ldg(&g_off2[rg[i]]) : 0;
                eb[i] = ok ? __ldg(&g_off2[rg[i] + 1]) : 0;
            }
            int src[4][4];
#pragma unroll
            for (int i = 0; i < 4; i++) {
                int d = eb[i] - ea[i];
#pragma unroll
                for (int j = 0; j < 4; j++) {
                    int idx = ea[i] + ((j < d) ? j : 0);
                    src[i][j] = (d > 0) ? __ldg(&g_pack2[idx]) : 0;
                }
            }
            float4 vv[4];
#pragma unroll
            for (int i = 0; i < 4; i++) {
                float4 v = make_float4(0.f, 0.f, 0.f, 0.f);
                if (rg[i] < NN) {
                    float4 hv = *(const float4*)(g_HIN + (size_t)rg[i] * HH + c0);
                    v.x = epsl * hv.x; v.y = epsl * hv.y;
                    v.z = epsl * hv.z; v.w = epsl * hv.w;
                }
                vv[i] = v;
            }
#pragma unroll
            for (int j = 0; j < 4; j++) {
#pragma unroll
                for (int i = 0; i < 4; i++) {
                    if (j < eb[i] - ea[i]) {
                        float4 a = *(const float4*)(g_HIN + (size_t)src[i][j] * HH + c0);
                        vv[i].x += a.x; vv[i].y += a.y;
                        vv[i].z += a.z; vv[i].w += a.w;
                    }
                }
            }
#pragma unroll
            for (int i = 0; i < 4; i++) {
                for (int e = ea[i] + 4; e < eb[i]; e++) {
                    int s0 = __ldg(&g_pack2[e]);
                    float4 a = *(const float4*)(g_HIN + (size_t)s0 * HH + c0);
                    vv[i].x += a.x; vv[i].y += a.y;
                    vv[i].z += a.z; vv[i].w += a.w;
                }
            }
#pragma unroll
            for (int i = 0; i < 4; i++) {
                int r = (g * 4 + i) * 8 + w;
                float fv[4] = {vv[i].x, vv[i].y, vv[i].z, vv[i].w};
                __nv_bfloat16 hb[4], lb[4];
#pragma unroll
                for (int j = 0; j < 4; j++) {
                    hb[j] = __float2bfloat16(fv[j]);
                    lb[j] = __float2bfloat16(fv[j] - __bfloat162float(hb[j]));
                }
                *(uint2*)(Ah + r * PAD + c0) = *(uint2*)hb;
                *(uint2*)(Al + r * PAD + c0) = *(uint2*)lb;
            }
        }
    } else {
#pragma unroll
        for (int it = 0; it < 8; it++) {
            int r = it * 8 + w;
            int grow = m0 + r;
            float4 v = make_float4(0.f, 0.f, 0.f, 0.f);
            if (grow < NN) {
                float4 y = *(const float4*)(g_Y1 + (size_t)grow * HH + c0);
                v.x = fmaxf(fmaf(s_sc[c0 + 0], y.x, s_sh[c0 + 0]), 0.f);
                v.y = fmaxf(fmaf(s_sc[c0 + 1], y.y, s_sh[c0 + 1]), 0.f);
                v.z = fmaxf(fmaf(s_sc[c0 + 2], y.z, s_sh[c0 + 2]), 0.f);
                v.w = fmaxf(fmaf(s_sc[c0 + 3], y.w, s_sh[c0 + 3]), 0.f);
            }
            float fv[4] = {v.x, v.y, v.z, v.w};
            __nv_bfloat16 hb[4], lb[4];
#pragma unroll
            for (int j = 0; j < 4; j++) {
                hb[j] = __float2bfloat16(fv[j]);
                lb[j] = __float2bfloat16(fv[j] - __bfloat162float(hb[j]));
            }
            *(uint2*)(Ah + r * PAD + c0) = *(uint2*)hb;
            *(uint2*)(Al + r * PAD + c0) = *(uint2*)lb;
        }
    }
    __syncthreads();

    float acc[2][4][4];
#pragma unroll
    for (int mi = 0; mi < 2; mi++)
#pragma unroll
        for (int nb = 0; nb < 4; nb++)
#pragma unroll
            for (int j = 0; j < 4; j++) acc[mi][nb][j] = 0.f;

    const int aRow = wm * 32 + (lane & 15);
    const int aKs = (lane >> 4) * 8;
    const int bN = wn * 32 + (lane >> 4) * 8 + (lane & 7);
    const int bKs = ((lane >> 3) & 1) * 8;

    // ---- pass 1: acc += Ah*Bh + Al*Bh ----
#pragma unroll
    for (int ks = 0; ks < 8; ks++) {
        uint32_t ah[2][4], al[2][4], bbq[2][4];
#pragma unroll
        for (int mi = 0; mi < 2; mi++) {
            uint32_t ra = (uint32_t)(((aRow + mi * 16) * PAD + ks * 16 + aKs) * 2);
            ldsm4(ah[mi], Ah_u + ra);
            ldsm4(al[mi], Al_u + ra);
        }
#pragma unroll
        for (int nb2 = 0; nb2 < 2; nb2++) {
            uint32_t rb = (uint32_t)(((bN + nb2 * 16) * PAD + ks * 16 + bKs) * 2);
            ldsm4(bbq[nb2], B_u + rb);
        }
#pragma unroll
        for (int mi = 0; mi < 2; mi++)
#pragma unroll
            for (int nb = 0; nb < 4; nb++) {
                const uint32_t* bp = &bbq[nb >> 1][(nb & 1) * 2];
                mma16816(acc[mi][nb], ah[mi], bp);
                mma16816(acc[mi][nb], al[mi], bp);
            }
    }
    __syncthreads();   // all warps done reading Bh

    // ---- pass-2 W tile: lo ----
#pragma unroll
    for (int it = 0; it < 8; it++) {
        int q = it * 256 + tid;
        int n = q >> 4, k0 = (q & 15) * 8;
        *(uint4*)(Bs + n * PAD + k0) = *(const uint4*)(wl + n * HH + k0);
    }
    __syncthreads();

    // ---- pass 2: acc += Ah*Bl ----
#pragma unroll
    for (int ks = 0; ks < 8; ks++) {
        uint32_t ah[2][4], bbq[2][4];
#pragma unroll
        for (int mi = 0; mi < 2; mi++) {
            uint32_t ra = (uint32_t)(((aRow + mi * 16) * PAD + ks * 16 + aKs) * 2);
            ldsm4(ah[mi], Ah_u + ra);
        }
#pragma unroll
        for (int nb2 = 0; nb2 < 2; nb2++) {
            uint32_t rb = (uint32_t)(((bN + nb2 * 16) * PAD + ks * 16 + bKs) * 2);
            ldsm4(bbq[nb2], B_u + rb);
        }
#pragma unroll
        for (int mi = 0; mi < 2; mi++)
#pragma unroll
            for (int nb = 0; nb < 4; nb++)
                mma16816(acc[mi][nb], ah[mi], &bbq[nb >> 1][(nb & 1) * 2]);
    }

    // ---- epilogue: bias, store, per-column stats ----
    float* outp = (MODE == 1) ? g_Y1 : g_P;
    float cs[4][2], cq[4][2];
#pragma unroll
    for (int nb = 0; nb < 4; nb++) { cs[nb][0] = cs[nb][1] = 0.f; cq[nb][0] = cq[nb][1] = 0.f; }
    float bse[4][2];
#pragma unroll
    for (int nb = 0; nb < 4; nb++) {
        int c = wn * 32 + nb * 8 + (lane & 3) * 2;
        bse[nb][0] = __ldg(bias + c);
        bse[nb][1] = __ldg(bias + c + 1);
    }
#pragma unroll
    for (int mi = 0; mi < 2; mi++) {
        int r0 = m0 + wm * 32 + mi * 16 + (lane >> 2);
        int r1 = r0 + 8;
        bool v0 = r0 < NN, v1 = r1 < NN;
#pragma unroll
        for (int nb = 0; nb < 4; nb++) {
            int c = wn * 32 + nb * 8 + (lane & 3) * 2;
            float o0 = acc[mi][nb][0] + bse[nb][0];
            float o1 = acc[mi][nb][1] + bse[nb][1];
            float o2 = acc[mi][nb][2] + bse[nb][0];
            float o3 = acc[mi][nb][3] + bse[nb][1];
            if (v0) {
                *(float2*)(outp + (size_t)r0 * HH + c) = make_float2(o0, o1);
                cs[nb][0] += o0; cs[nb][1] += o1;
                cq[nb][0] += o0 * o0; cq[nb][1] += o1 * o1;
            }
            if (v1) {
                *(float2*)(outp + (size_t)r1 * HH + c) = make_float2(o2, o3);
                cs[nb][0] += o2; cs[nb][1] += o3;
                cq[nb][0] += o2 * o2; cq[nb][1] += o3 * o3;
            }
        }
    }
#pragma unroll
    for (int nb = 0; nb < 4; nb++) {
#pragma unroll
        for (int j = 0; j < 2; j++) {
            float s = cs[nb][j], q = cq[nb][j];
#pragma unroll
            for (int off = 16; off >= 4; off >>= 1) {
                s += __shfl_down_sync(0xffffffffu, s, off);
                q += __shfl_down_sync(0xffffffffu, q, off);
            }
            if (lane < 4) {
                int c = wn * 32 + nb * 8 + lane * 2 + j;
                sS[wm * HH + c] = s;
                sQ[wm * HH + c] = q;
            }
        }
    }
    __syncthreads();
    if (tid < HH) {
        float s = sS[tid] + sS[HH + tid];
        float q = sQ[tid] + sQ[HH + tid];
        float* st = g_stats + ((MODE == 1) ? 0 : 2 * HH);
        atomicAdd(st + tid, s);
        atomicAdd(st + HH + tid, q);
    }
}

// pool: BN2 of last layer finalized per-block, scatter to g_pool
__global__ void __launch_bounds__(256)
k_pool(const int* __restrict__ batch,
       const float* __restrict__ bg, const float* __restrict__ bb) {
    __shared__ float s_sc[HH], s_sh[HH];
    const int tid = threadIdx.x;
    if (tid < HH) {
        float mu  = g_stats[2 * HH + tid] * (1.f / (float)NN);
        float msq = g_stats[3 * HH + tid] * (1.f / (float)NN);
        float rstd = rsqrtf(msq - mu * mu + 1e-5f);
        float s = __ldg(bg + tid) * rstd;
        s_sc[tid] = s;
        s_sh[tid] = __ldg(bb + tid) - s * mu;
    }
    __syncthreads();
    const int n = blockIdx.x * 8 + (tid >> 5);
    if (n >= NN) return;
    const int c = (tid & 31) << 2;
    float4 y = *(const float4*)(g_P + (size_t)n * HH + c);
    float4 o;
    o.x = fmaf(s_sc[c + 0], y.x, s_sh[c + 0]);
    o.y = fmaf(s_sc[c + 1], y.y, s_sh[c + 1]);
    o.z = fmaf(s_sc[c + 2], y.z, s_sh[c + 2]);
    o.w = fmaf(s_sc[c + 3], y.w, s_sh[c + 3]);
    red_add_v4(g_pool + (size_t)__ldg(batch + n) * HH + c, o);
}

__global__ void k_final(const float* __restrict__ cw1, const float* __restrict__ cb1,
                        const float* __restrict__ cw2, const float* __restrict__ cb2,
                        float* __restrict__ out) {
    __shared__ float p[HH];
    __shared__ float rb[4];
    int j = threadIdx.x;
    p[j] = g_pool[(size_t)blockIdx.x * HH + j];
    __syncthreads();
    float acc = __ldg(cb1 + j);
#pragma unroll 8
    for (int i = 0; i < HH; i++)
        acc = fmaf(p[i], __ldg(cw1 + i * HH + j), acc);
    float v = fmaxf(acc, 0.f) * __ldg(cw2 + j);
#pragma unroll
    for (int off = 16; off > 0; off >>= 1)
        v += __shfl_down_sync(0xffffffffu, v, off);
    if ((j & 31) == 0) rb[j >> 5] = v;
    __syncthreads();
    if (j == 0) out[blockIdx.x] = rb[0] + rb[1] + rb[2] + rb[3] + __ldg(cb2);
}

extern "C" void kernel_launch(void* const* d_in, const int* in_sizes, int n_in,
                              void* d_out, int out_size) {
    const int*   x     = (const int*)d_in[0];
    const int*   ei    = (const int*)d_in[1];
    const int*   ea    = (const int*)d_in[2];
    const int*   batch = (const int*)d_in[3];
    const float* aemb  = (const float*)d_in[4];
    const float* bemb  = (const float*)d_in[5];
    const float* eps   = (const float*)d_in[6];
    const float* w1    = (const float*)d_in[7];
    const float* b1    = (const float*)d_in[8];
    const float* bn1g  = (const float*)d_in[9];
    const float* bn1b  = (const float*)d_in[10];
    const float* w2    = (const float*)d_in[11];
    const float* b2    = (const float*)d_in[12];
    const float* bng   = (const float*)d_in[13];
    const float* bnb   = (const float*)d_in[14];
    const float* cw1   = (const float*)d_in[15];
    const float* cb1   = (const float*)d_in[16];
    const float* cw2   = (const float*)d_in[17];
    const float* cb2   = (const float*)d_in[18];
    float* out = (float*)d_out;
    const int* row = ei;
    const int* col = ei + EE;

    cudaFuncSetAttribute(k_mma<1>, cudaFuncAttributeMaxDynamicSharedMemorySize, GEMM_SMEM);
    cudaFuncSetAttribute(k_mma<2>, cudaFuncAttributeMaxDynamicSharedMemorySize, GEMM_SMEM);

    // zero counters/pool via async memsets (graph-capturable; no allocation)
    void *p_cnt, *p_cur, *p_cnt2, *p_cur2, *p_pool;
    cudaGetSymbolAddress(&p_cnt, g_cnt);
    cudaGetSymbolAddress(&p_cur, g_cur);
    cudaGetSymbolAddress(&p_cnt2, g_cnt2);
    cudaGetSymbolAddress(&p_cur2, g_cur2);
    cudaGetSymbolAddress(&p_pool, g_pool);
    cudaMemsetAsync(p_cnt, 0, NN * sizeof(int));
    cudaMemsetAsync(p_cur, 0, NN * sizeof(int));
    cudaMemsetAsync(p_cnt2, 0, NN * sizeof(int));
    cudaMemsetAsync(p_cur2, 0, NN * sizeof(int));
    cudaMemsetAsync(p_pool, 0, (size_t)GG * HH * sizeof(float));

    const int NT = 256;
    const int gridE  = (EE + NT - 1) / NT;        // 2344
    const int gridGEMM = (NN + 63) / 64;          // 4688
    const int gridNode = (NN + 7) / 8;            // 37500

    k_prepall<<<3044, NT>>>(w1, w2, bemb, row, col);   // launch 0
    k_scan<<<2, 1024>>>();                             // launch 1
    k_fill<<<gridE, NT>>>(row, col, ea);               // launch 2
    for (int l = 0; l < 5; l++) {
        if (l == 0)
            k_node<1><<<gridNode, NT>>>(0, nullptr, nullptr, x, aemb);  // launch 3: profiled
        else
            k_node<0><<<gridNode, NT>>>(l, bng + (l - 1) * HH, bnb + (l - 1) * HH,
                                        nullptr, nullptr);
        k_mma<1><<<gridGEMM, NT, GEMM_SMEM>>>(2 * l, b1 + l * HH, eps + l, nullptr, nullptr);
        k_mma<2><<<gridGEMM, NT, GEMM_SMEM>>>(2 * l + 1, b2 + l * HH, nullptr,
                                              bn1g + l * HH, bn1b + l * HH);
    }
    k_pool<<<gridNode, NT>>>(batch, bng + 4 * HH, bnb + 4 * HH);
    k_final<<<GG, HH>>>(cw1, cb1, cw2, cb2, out);
}

// round 17
// speedup vs baseline: 1.0610x; 1.0135x over previous
#include <cuda_runtime.h>
#include <cuda_bf16.h>
#include <cstdint>

#define NN 300000
#define EE 600000
#define HH 128
#define GG 8192

// ---------------- scratch (device globals: allocation-free) ----------------
__device__ float g_P[(size_t)NN * HH];    // prev-layer raw output (y2 pre-BN)
__device__ float g_HIN[(size_t)NN * HH];  // h_in (fp32 — required by Al split term)
__device__ float g_Y1[(size_t)NN * HH];   // y1 (pre-BN1 GEMM1 output)
__device__ float g_pool[(size_t)GG * HH];
__device__ float g_stats[4 * HH];         // [sum1, sumsq1 | sum2, sumsq2]
__device__ __nv_bfloat16 g_Wh[10 * HH * HH];
__device__ __nv_bfloat16 g_Wl[10 * HH * HH];
// CSR by row (payload cidx) for bond sums; CSC by col (payload row) for aggr gather
__device__ int g_cnt[NN],  g_cur[NN],  g_off[NN + 1];
__device__ int g_cnt2[NN], g_cur2[NN], g_off2[NN + 1];
__device__ unsigned int g_pack[EE];    // cidx (bond table index)
__device__ int g_pack2[EE];            // src row
// precombined bond tables: [5][216][128]
__device__ float g_ctab[5 * 216 * HH];

__device__ __forceinline__ void red_add_v4(float* p, float4 v) {
    asm volatile("red.global.add.v4.f32 [%0], {%1,%2,%3,%4};"
                 :: "l"(p), "f"(v.x), "f"(v.y), "f"(v.z), "f"(v.w) : "memory");
}
__device__ __forceinline__ uint32_t smem_u32(const void* p) {
    uint32_t a;
    asm("{ .reg .u64 t; cvta.to.shared.u64 t, %1; cvt.u32.u64 %0, t; }" : "=r"(a) : "l"(p));
    return a;
}
__device__ __forceinline__ void ldsm4(uint32_t* r, uint32_t addr) {
    asm volatile("ldmatrix.sync.aligned.m8n8.x4.shared.b16 {%0,%1,%2,%3}, [%4];"
                 : "=r"(r[0]), "=r"(r[1]), "=r"(r[2]), "=r"(r[3]) : "r"(addr));
}
__device__ __forceinline__ void mma16816(float* d, const uint32_t* a, const uint32_t* b) {
    asm volatile("mma.sync.aligned.m16n8k16.row.col.f32.bf16.bf16.f32 "
                 "{%0,%1,%2,%3}, {%4,%5,%6,%7}, {%8,%9}, {%0,%1,%2,%3};"
                 : "+f"(d[0]), "+f"(d[1]), "+f"(d[2]), "+f"(d[3])
                 : "r"(a[0]), "r"(a[1]), "r"(a[2]), "r"(a[3]), "r"(b[0]), "r"(b[1]));
}

// ---------------- merged setup: prepw + prepbond + cnt ----------------
__global__ void k_prepall(const float* __restrict__ w1, const float* __restrict__ w2,
                          const float* __restrict__ bemb,
                          const int* __restrict__ row, const int* __restrict__ col) {
    const int bid = blockIdx.x, tid = threadIdx.x;
    if (bid < 160) {
        int q = bid * 256 + tid;          // [0, 40960)
        int l = q >> 12;                  // 0..9
        int r = q & 4095;
        const float* W = (l < 5) ? (w1 + (size_t)l * HH * HH)
                                 : (w2 + (size_t)(l - 5) * HH * HH);
        int slot = (l < 5) ? (2 * l) : (2 * (l - 5) + 1);
        int k = r >> 5, n0 = (r & 31) * 4;
        float4 w = *(const float4*)(W + (size_t)k * HH + n0);
        float wv[4] = {w.x, w.y, w.z, w.w};
#pragma unroll
        for (int j = 0; j < 4; j++) {
            __nv_bfloat16 h = __float2bfloat16(wv[j]);
            size_t o = (size_t)slot * HH * HH + (size_t)(n0 + j) * HH + k;
            g_Wh[o] = h;
            g_Wl[o] = __float2bfloat16(wv[j] - __bfloat162float(h));
        }
    } else if (bid < 700) {
        int idx = (bid - 160) * 256 + tid;   // [0, 138240)
        int l = idx / 27648;
        int rem = idx % 27648;
        int c = rem >> 7, h = rem & 127;
        int a0 = c / 36, a1 = (c / 6) % 6, a2 = c % 6;
        const float* b = bemb + (size_t)l * 3 * 8 * HH;
        g_ctab[((size_t)l * 216 + c) * HH + h] =
            b[(size_t)(0 * 8 + a0) * HH + h] + b[(size_t)(1 * 8 + a1) * HH + h]
            + b[(size_t)(2 * 8 + a2) * HH + h];
    } else {
        int e = (bid - 700) * 256 + tid;
        if (e < EE) {
            atomicAdd(&g_cnt[__ldg(row + e)], 1);
            atomicAdd(&g_cnt2[__ldg(col + e)], 1);
        }
    }
}

// exclusive scan: block 0 -> (cnt,off), block 1 -> (cnt2,off2)
__global__ void k_scan() {
    __shared__ int bs[1024];
    const int* cnt = (blockIdx.x == 0) ? g_cnt : g_cnt2;
    int* off = (blockIdx.x == 0) ? g_off : g_off2;
    const int t = threadIdx.x;
    const int C = (NN + 1023) / 1024;   // 293
    int base = t * C;
    int s = 0;
    for (int i = 0; i < C; i++) {
        int idx = base + i;
        if (idx < NN) s += cnt[idx];
    }
    bs[t] = s;
    __syncthreads();
    for (int o = 1; o < 1024; o <<= 1) {
        int u = (t >= o) ? bs[t - o] : 0;
        __syncthreads();
        bs[t] += u;
        __syncthreads();
    }
    int run = bs[t] - s;
    for (int i = 0; i < C; i++) {
        int idx = base + i;
        if (idx < NN) { off[idx] = run; run += cnt[idx]; }
    }
    if (t == 1023) off[NN] = EE;
}

__global__ void k_fill(const int* __restrict__ row, const int* __restrict__ col,
                       const int* __restrict__ eattr) {
    int e = blockIdx.x * blockDim.x + threadIdx.x;
    if (e >= EE) return;
    int r = __ldg(row + e);
    int c = __ldg(col + e);
    int a0 = __ldg(eattr + e * 3 + 0);
    int a1 = __ldg(eattr + e * 3 + 1);
    int a2 = __ldg(eattr + e * 3 + 2);
    int pos = g_off[r] + atomicAdd(&g_cur[r], 1);
    g_pack[pos] = (unsigned int)(a0 * 36 + a1 * 6 + a2);
    int pos2 = g_off2[c] + atomicAdd(&g_cur2[c], 1);
    g_pack2[pos2] = r;
}

// ---------------- node kernel v3: HALF-WARP per node ----------------
// 16 lanes x 8 floats (two contiguous float4 segments c, c+64) per node.
// Per-thread MLP x2 in every phase; bond loop iterations shared across
// 2 nodes (max(d0,d1) covers both). Prev-act chain hoisted above bond loop.
template<int FIRST>
__global__ void __launch_bounds__(256)
k_node(int layer, const float* __restrict__ bg, const float* __restrict__ bb,
       const int* __restrict__ x, const float* __restrict__ aemb) {
    __shared__ float s_sc[HH], s_sh[HH];
    const int tid = threadIdx.x;
    if (blockIdx.x == 0 && tid < 2 * HH) g_stats[tid] = 0.f;   // zero slot0
    if (!FIRST) {
        if (tid < HH) {
            float mu  = g_stats[2 * HH + tid] * (1.f / (float)NN);
            float msq = g_stats[3 * HH + tid] * (1.f / (float)NN);
            float rstd = rsqrtf(msq - mu * mu + 1e-5f);
            float s = __ldg(bg + tid) * rstd;
            s_sc[tid] = s;
            s_sh[tid] = __ldg(bb + tid) - s * mu;
        }
        __syncthreads();
    }
    const int lane = tid & 31;
    const int half = lane >> 4, l = lane & 15;
    const int n = blockIdx.x * 16 + (tid >> 5) * 2 + half;
    if (n >= NN) return;
    const int c1 = l * 4, c2 = 64 + l * 4;
    const float* ctab = g_ctab + (size_t)layer * 216 * HH;
    const int e0 = __ldg(&g_off[n]), e1 = __ldg(&g_off[n + 1]);
    const float inv = 1.f / ((float)(e1 - e0) + 1.f);

    // ---- prev-activation chain FIRST (independent of bond loop) ----
    float4 p1, p2;
    if (FIRST) {
        p1 = make_float4(0.f, 0.f, 0.f, 0.f);
        p2 = make_float4(0.f, 0.f, 0.f, 0.f);
#pragma unroll
        for (int f = 0; f < 9; f++) {
            int xi = __ldg(x + n * 9 + f);
            const float* er = aemb + (size_t)(f * 128 + xi) * HH;
            const float4 a = *(const float4*)(er + c1);
            const float4 b = *(const float4*)(er + c2);
            p1.x += a.x; p1.y += a.y; p1.z += a.z; p1.w += a.w;
            p2.x += b.x; p2.y += b.y; p2.z += b.z; p2.w += b.w;
        }
    } else {
        p1 = *(const float4*)(g_P + (size_t)n * HH + c1);
        p2 = *(const float4*)(g_P + (size_t)n * HH + c2);
    }

    // ---- bond gather loop (2 independent chains per thread) ----
    float4 b1 = make_float4(0.f, 0.f, 0.f, 0.f);
    float4 b2 = make_float4(0.f, 0.f, 0.f, 0.f);
    for (int e = e0; e < e1; e++) {
        unsigned int ci = __ldg(&g_pack[e]);
        const float* tr = ctab + (size_t)ci * HH;
        const float4 t1 = *(const float4*)(tr + c1);
        const float4 t2 = *(const float4*)(tr + c2);
        b1.x += t1.x; b1.y += t1.y; b1.z += t1.z; b1.w += t1.w;
        b2.x += t2.x; b2.y += t2.y; b2.z += t2.z; b2.w += t2.w;
    }

    if (!FIRST) {
        p1.x = fmaxf(fmaf(s_sc[c1 + 0], p1.x, s_sh[c1 + 0]), 0.f);
        p1.y = fmaxf(fmaf(s_sc[c1 + 1], p1.y, s_sh[c1 + 1]), 0.f);
        p1.z = fmaxf(fmaf(s_sc[c1 + 2], p1.z, s_sh[c1 + 2]), 0.f);
        p1.w = fmaxf(fmaf(s_sc[c1 + 3], p1.w, s_sh[c1 + 3]), 0.f);
        p2.x = fmaxf(fmaf(s_sc[c2 + 0], p2.x, s_sh[c2 + 0]), 0.f);
        p2.y = fmaxf(fmaf(s_sc[c2 + 1], p2.y, s_sh[c2 + 1]), 0.f);
        p2.z = fmaxf(fmaf(s_sc[c2 + 2], p2.z, s_sh[c2 + 2]), 0.f);
        p2.w = fmaxf(fmaf(s_sc[c2 + 3], p2.w, s_sh[c2 + 3]), 0.f);
    }
    float4 h1, h2;
    h1.x = fmaf(b1.x, inv, p1.x); h1.y = fmaf(b1.y, inv, p1.y);
    h1.z = fmaf(b1.z, inv, p1.z); h1.w = fmaf(b1.w, inv, p1.w);
    h2.x = fmaf(b2.x, inv, p2.x); h2.y = fmaf(b2.y, inv, p2.y);
    h2.z = fmaf(b2.z, inv, p2.z); h2.w = fmaf(b2.w, inv, p2.w);
    *(float4*)(g_HIN + (size_t)n * HH + c1) = h1;
    *(float4*)(g_HIN + (size_t)n * HH + c2) = h2;
}

// ---------------- HMMA bf16-split GEMM, M-tile 64, two-pass B, 3 CTAs/SM ----
#define PAD 136
#define GEMM_SMEM 71680

template<int MODE>
__global__ void __launch_bounds__(256, 3)
k_mma(int wslot, const float* __restrict__ bias,
      const float* __restrict__ epsp,
      const float* __restrict__ bg, const float* __restrict__ bb) {
    extern __shared__ char dsm[];
    __shared__ float s_sc[HH], s_sh[HH];

    const uint32_t su = smem_u32(dsm);
    const uint32_t Ah_u = su, Al_u = su + 17408;
    const uint32_t B_u = su + 34816;
    __nv_bfloat16* Ah = (__nv_bfloat16*)dsm;
    __nv_bfloat16* Al = (__nv_bfloat16*)(dsm + 17408);
    __nv_bfloat16* Bs = (__nv_bfloat16*)(dsm + 34816);
    float* sS = (float*)(dsm + 69632);   // [2][128]
    float* sQ = (float*)(dsm + 70656);   // [2][128]

    const int tid = threadIdx.x;
    const int wid = tid >> 5, lane = tid & 31;
    const int wm = wid & 1, wn = wid >> 1;
    const int m0 = blockIdx.x * 64;

    if (MODE == 1 && blockIdx.x == 0 && tid < 2 * HH)
        g_stats[2 * HH + tid] = 0.f;   // zero slot1 for upcoming GEMM2
    if (MODE == 2 && tid < HH) {
        float mu  = g_stats[tid] * (1.f / (float)NN);
        float msq = g_stats[HH + tid] * (1.f / (float)NN);
        float rstd = rsqrtf(msq - mu * mu + 1e-5f);
        float s = __ldg(bg + tid) * rstd;
        s_sc[tid] = s;
        s_sh[tid] = __ldg(bb + tid) - s * mu;
    }
    const float epsl = (MODE == 1) ? (1.f + __ldg(epsp)) : 0.f;
    if (MODE == 2) __syncthreads();

    // ---- pass-1 W tile: hi ----
    const __nv_bfloat16* wh = g_Wh + (size_t)wslot * HH * HH;
    const __nv_bfloat16* wl = g_Wl + (size_t)wslot * HH * HH;
#pragma unroll
    for (int it = 0; it < 8; it++) {
        int q = it * 256 + tid;
        int n = q >> 4, k0 = (q & 15) * 8;
        *(uint4*)(Bs + n * PAD + k0) = *(const uint4*)(wh + n * HH + k0);
    }

    // ---- A: load + transform + split ----
    const int w = tid >> 5;
    const int c0 = (tid & 31) * 4;
    if (MODE == 1) {
#pragma unroll
        for (int g = 0; g < 2; g++) {
            int rg[4], ea[4], eb[4];
#pragma unroll
            for (int i = 0; i < 4; i++) {
                rg[i] = m0 + (g * 4 + i) * 8 + w;
                bool ok = rg[i] < NN;
                ea[i] = ok ? __ldg(&g_off2[rg[i]]) : 0;
                eb[i] = ok ? __ldg(&g_off2[rg[i] + 1]) : 0;
            }
            int src[4][4];
#pragma unroll
            for (int i = 0; i < 4; i++) {
                int d = eb[i] - ea[i];
#pragma unroll
                for (int j = 0; j < 4; j++) {
                    int idx = ea[i] + ((j < d) ? j : 0);
                    src[i][j] = (d > 0) ? __ldg(&g_pack2[idx]) : 0;
                }
            }
            float4 vv[4];
#pragma unroll
            for (int i = 0; i < 4; i++) {
                float4 v = make_float4(0.f, 0.f, 0.f, 0.f);
                if (rg[i] < NN) {
                    float4 hv = *(const float4*)(g_HIN + (size_t)rg[i] * HH + c0);
                    v.x = epsl * hv.x; v.y = epsl * hv.y;
                    v.z = epsl * hv.z; v.w = epsl * hv.w;
                }
                vv[i] = v;
            }
#pragma unroll
            for (int j = 0; j < 4; j++) {
#pragma unroll
                for (int i = 0; i < 4; i++) {
                    if (j < eb[i] - ea[i]) {
                        float4 a = *(const float4*)(g_HIN + (size_t)src[i][j] * HH + c0);
                        vv[i].x += a.x; vv[i].y += a.y;
                        vv[i].z += a.z; vv[i].w += a.w;
                    }
                }
            }
#pragma unroll
            for (int i = 0; i < 4; i++) {
                for (int e = ea[i] + 4; e < eb[i]; e++) {
                    int s0 = __ldg(&g_pack2[e]);
                    float4 a = *(const float4*)(g_HIN + (size_t)s0 * HH + c0);
                    vv[i].x += a.x; vv[i].y += a.y;
                    vv[i].z += a.z; vv[i].w += a.w;
                }
            }
#pragma unroll
            for (int i = 0; i < 4; i++) {
                int r = (g * 4 + i) * 8 + w;
                float fv[4] = {vv[i].x, vv[i].y, vv[i].z, vv[i].w};
                __nv_bfloat16 hb[4], lb[4];
#pragma unroll
                for (int j = 0; j < 4; j++) {
                    hb[j] = __float2bfloat16(fv[j]);
                    lb[j] = __float2bfloat16(fv[j] - __bfloat162float(hb[j]));
                }
                *(uint2*)(Ah + r * PAD + c0) = *(uint2*)hb;
                *(uint2*)(Al + r * PAD + c0) = *(uint2*)lb;
            }
        }
    } else {
#pragma unroll
        for (int it = 0; it < 8; it++) {
            int r = it * 8 + w;
            int grow = m0 + r;
            float4 v = make_float4(0.f, 0.f, 0.f, 0.f);
            if (grow < NN) {
                float4 y = *(const float4*)(g_Y1 + (size_t)grow * HH + c0);
                v.x = fmaxf(fmaf(s_sc[c0 + 0], y.x, s_sh[c0 + 0]), 0.f);
                v.y = fmaxf(fmaf(s_sc[c0 + 1], y.y, s_sh[c0 + 1]), 0.f);
                v.z = fmaxf(fmaf(s_sc[c0 + 2], y.z, s_sh[c0 + 2]), 0.f);
                v.w = fmaxf(fmaf(s_sc[c0 + 3], y.w, s_sh[c0 + 3]), 0.f);
            }
            float fv[4] = {v.x, v.y, v.z, v.w};
            __nv_bfloat16 hb[4], lb[4];
#pragma unroll
            for (int j = 0; j < 4; j++) {
                hb[j] = __float2bfloat16(fv[j]);
                lb[j] = __float2bfloat16(fv[j] - __bfloat162float(hb[j]));
            }
            *(uint2*)(Ah + r * PAD + c0) = *(uint2*)hb;
            *(uint2*)(Al + r * PAD + c0) = *(uint2*)lb;
        }
    }
    __syncthreads();

    float acc[2][4][4];
#pragma unroll
    for (int mi = 0; mi < 2; mi++)
#pragma unroll
        for (int nb = 0; nb < 4; nb++)
#pragma unroll
            for (int j = 0; j < 4; j++) acc[mi][nb][j] = 0.f;

    const int aRow = wm * 32 + (lane & 15);
    const int aKs = (lane >> 4) * 8;
    const int bN = wn * 32 + (lane >> 4) * 8 + (lane & 7);
    const int bKs = ((lane >> 3) & 1) * 8;

    // ---- pass 1: acc += Ah*Bh + Al*Bh ----
#pragma unroll
    for (int ks = 0; ks < 8; ks++) {
        uint32_t ah[2][4], al[2][4], bbq[2][4];
#pragma unroll
        for (int mi = 0; mi < 2; mi++) {
            uint32_t ra = (uint32_t)(((aRow + mi * 16) * PAD + ks * 16 + aKs) * 2);
            ldsm4(ah[mi], Ah_u + ra);
            ldsm4(al[mi], Al_u + ra);
        }
#pragma unroll
        for (int nb2 = 0; nb2 < 2; nb2++) {
            uint32_t rb = (uint32_t)(((bN + nb2 * 16) * PAD + ks * 16 + bKs) * 2);
            ldsm4(bbq[nb2], B_u + rb);
        }
#pragma unroll
        for (int mi = 0; mi < 2; mi++)
#pragma unroll
            for (int nb = 0; nb < 4; nb++) {
                const uint32_t* bp = &bbq[nb >> 1][(nb & 1) * 2];
                mma16816(acc[mi][nb], ah[mi], bp);
                mma16816(acc[mi][nb], al[mi], bp);
            }
    }
    __syncthreads();   // all warps done reading Bh

    // ---- pass-2 W tile: lo ----
#pragma unroll
    for (int it = 0; it < 8; it++) {
        int q = it * 256 + tid;
        int n = q >> 4, k0 = (q & 15) * 8;
        *(uint4*)(Bs + n * PAD + k0) = *(const uint4*)(wl + n * HH + k0);
    }
    __syncthreads();

    // ---- pass 2: acc += Ah*Bl ----
#pragma unroll
    for (int ks = 0; ks < 8; ks++) {
        uint32_t ah[2][4], bbq[2][4];
#pragma unroll
        for (int mi = 0; mi < 2; mi++) {
            uint32_t ra = (uint32_t)(((aRow + mi * 16) * PAD + ks * 16 + aKs) * 2);
            ldsm4(ah[mi], Ah_u + ra);
        }
#pragma unroll
        for (int nb2 = 0; nb2 < 2; nb2++) {
            uint32_t rb = (uint32_t)(((bN + nb2 * 16) * PAD + ks * 16 + bKs) * 2);
            ldsm4(bbq[nb2], B_u + rb);
        }
#pragma unroll
        for (int mi = 0; mi < 2; mi++)
#pragma unroll
            for (int nb = 0; nb < 4; nb++)
                mma16816(acc[mi][nb], ah[mi], &bbq[nb >> 1][(nb & 1) * 2]);
    }

    // ---- epilogue: bias, store, per-column stats ----
    float* outp = (MODE == 1) ? g_Y1 : g_P;
    float cs[4][2], cq[4][2];
#pragma unroll
    for (int nb = 0; nb < 4; nb++) { cs[nb][0] = cs[nb][1] = 0.f; cq[nb][0] = cq[nb][1] = 0.f; }
    float bse[4][2];
#pragma unroll
    for (int nb = 0; nb < 4; nb++) {
        int c = wn * 32 + nb * 8 + (lane & 3) * 2;
        bse[nb][0] = __ldg(bias + c);
        bse[nb][1] = __ldg(bias + c + 1);
    }
#pragma unroll
    for (int mi = 0; mi < 2; mi++) {
        int r0 = m0 + wm * 32 + mi * 16 + (lane >> 2);
        int r1 = r0 + 8;
        bool v0 = r0 < NN, v1 = r1 < NN;
#pragma unroll
        for (int nb = 0; nb < 4; nb++) {
            int c = wn * 32 + nb * 8 + (lane & 3) * 2;
            float o0 = acc[mi][nb][0] + bse[nb][0];
            float o1 = acc[mi][nb][1] + bse[nb][1];
            float o2 = acc[mi][nb][2] + bse[nb][0];
            float o3 = acc[mi][nb][3] + bse[nb][1];
            if (v0) {
                *(float2*)(outp + (size_t)r0 * HH + c) = make_float2(o0, o1);
                cs[nb][0] += o0; cs[nb][1] += o1;
                cq[nb][0] += o0 * o0; cq[nb][1] += o1 * o1;
            }
            if (v1) {
                *(float2*)(outp + (size_t)r1 * HH + c) = make_float2(o2, o3);
                cs[nb][0] += o2; cs[nb][1] += o3;
                cq[nb][0] += o2 * o2; cq[nb][1] += o3 * o3;
            }
        }
    }
#pragma unroll
    for (int nb = 0; nb < 4; nb++) {
#pragma unroll
        for (int j = 0; j < 2; j++) {
            float s = cs[nb][j], q = cq[nb][j];
#pragma unroll
            for (int off = 16; off >= 4; off >>= 1) {
                s += __shfl_down_sync(0xffffffffu, s, off);
                q += __shfl_down_sync(0xffffffffu, q, off);
            }
            if (lane < 4) {
                int c = wn * 32 + nb * 8 + lane * 2 + j;
                sS[wm * HH + c] = s;
                sQ[wm * HH + c] = q;
            }
        }
    }
    __syncthreads();
    if (tid < HH) {
        float s = sS[tid] + sS[HH + tid];
        float q = sQ[tid] + sQ[HH + tid];
        float* st = g_stats + ((MODE == 1) ? 0 : 2 * HH);
        atomicAdd(st + tid, s);
        atomicAdd(st + HH + tid, q);
    }
}

// pool: BN2 of last layer finalized per-block, scatter to g_pool
__global__ void __launch_bounds__(256)
k_pool(const int* __restrict__ batch,
       const float* __restrict__ bg, const float* __restrict__ bb) {
    __shared__ float s_sc[HH], s_sh[HH];
    const int tid = threadIdx.x;
    if (tid < HH) {
        float mu  = g_stats[2 * HH + tid] * (1.f / (float)NN);
        float msq = g_stats[3 * HH + tid] * (1.f / (float)NN);
        float rstd = rsqrtf(msq - mu * mu + 1e-5f);
        float s = __ldg(bg + tid) * rstd;
        s_sc[tid] = s;
        s_sh[tid] = __ldg(bb + tid) - s * mu;
    }
    __syncthreads();
    const int n = blockIdx.x * 8 + (tid >> 5);
    if (n >= NN) return;
    const int c = (tid & 31) << 2;
    float4 y = *(const float4*)(g_P + (size_t)n * HH + c);
    float4 o;
    o.x = fmaf(s_sc[c + 0], y.x, s_sh[c + 0]);
    o.y = fmaf(s_sc[c + 1], y.y, s_sh[c + 1]);
    o.z = fmaf(s_sc[c + 2], y.z, s_sh[c + 2]);
    o.w = fmaf(s_sc[c + 3], y.w, s_sh[c + 3]);
    red_add_v4(g_pool + (size_t)__ldg(batch + n) * HH + c, o);
}

__global__ void k_final(const float* __restrict__ cw1, const float* __restrict__ cb1,
                        const float* __restrict__ cw2, const float* __restrict__ cb2,
                        float* __restrict__ out) {
    __shared__ float p[HH];
    __shared__ float rb[4];
    int j = threadIdx.x;
    p[j] = g_pool[(size_t)blockIdx.x * HH + j];
    __syncthreads();
    float acc = __ldg(cb1 + j);
#pragma unroll 8
    for (int i = 0; i < HH; i++)
        acc = fmaf(p[i], __ldg(cw1 + i * HH + j), acc);
    float v = fmaxf(acc, 0.f) * __ldg(cw2 + j);
#pragma unroll
    for (int off = 16; off > 0; off >>= 1)
        v += __shfl_down_sync(0xffffffffu, v, off);
    if ((j & 31) == 0) rb[j >> 5] = v;
    __syncthreads();
    if (j == 0) out[blockIdx.x] = rb[0] + rb[1] + rb[2] + rb[3] + __ldg(cb2);
}

extern "C" void kernel_launch(void* const* d_in, const int* in_sizes, int n_in,
                              void* d_out, int out_size) {
    const int*   x     = (const int*)d_in[0];
    const int*   ei    = (const int*)d_in[1];
    const int*   ea    = (const int*)d_in[2];
    const int*   batch = (const int*)d_in[3];
    const float* aemb  = (const float*)d_in[4];
    const float* bemb  = (const float*)d_in[5];
    const float* eps   = (const float*)d_in[6];
    const float* w1    = (const float*)d_in[7];
    const float* b1    = (const float*)d_in[8];
    const float* bn1g  = (const float*)d_in[9];
    const float* bn1b  = (const float*)d_in[10];
    const float* w2    = (const float*)d_in[11];
    const float* b2    = (const float*)d_in[12];
    const float* bng   = (const float*)d_in[13];
    const float* bnb   = (const float*)d_in[14];
    const float* cw1   = (const float*)d_in[15];
    const float* cb1   = (const float*)d_in[16];
    const float* cw2   = (const float*)d_in[17];
    const float* cb2   = (const float*)d_in[18];
    float* out = (float*)d_out;
    const int* row = ei;
    const int* col = ei + EE;

    cudaFuncSetAttribute(k_mma<1>, cudaFuncAttributeMaxDynamicSharedMemorySize, GEMM_SMEM);
    cudaFuncSetAttribute(k_mma<2>, cudaFuncAttributeMaxDynamicSharedMemorySize, GEMM_SMEM);

    // zero counters/pool via async memsets (graph-capturable; no allocation)
    void *p_cnt, *p_cur, *p_cnt2, *p_cur2, *p_pool;
    cudaGetSymbolAddress(&p_cnt, g_cnt);
    cudaGetSymbolAddress(&p_cur, g_cur);
    cudaGetSymbolAddress(&p_cnt2, g_cnt2);
    cudaGetSymbolAddress(&p_cur2, g_cur2);
    cudaGetSymbolAddress(&p_pool, g_pool);
    cudaMemsetAsync(p_cnt, 0, NN * sizeof(int));
    cudaMemsetAsync(p_cur, 0, NN * sizeof(int));
    cudaMemsetAsync(p_cnt2, 0, NN * sizeof(int));
    cudaMemsetAsync(p_cur2, 0, NN * sizeof(int));
    cudaMemsetAsync(p_pool, 0, (size_t)GG * HH * sizeof(float));

    const int NT = 256;
    const int gridE  = (EE + NT - 1) / NT;        // 2344
    const int gridGEMM = (NN + 63) / 64;          // 4688
    const int gridNode = (NN + 15) / 16;          // 18750 (2 nodes/warp)
    const int gridPool = (NN + 7) / 8;            // 37500

    k_prepall<<<3044, NT>>>(w1, w2, bemb, row, col);   // launch 0
    k_scan<<<2, 1024>>>();                             // launch 1
    k_fill<<<gridE, NT>>>(row, col, ea);               // launch 2
    for (int l = 0; l < 5; l++) {
        if (l == 0)
            k_node<1><<<gridNode, NT>>>(0, nullptr, nullptr, x, aemb);  // launch 3: profiled
        else
            k_node<0><<<gridNode, NT>>>(l, bng + (l - 1) * HH, bnb + (l - 1) * HH,
                                        nullptr, nullptr);
        k_mma<1><<<gridGEMM, NT, GEMM_SMEM>>>(2 * l, b1 + l * HH, eps + l, nullptr, nullptr);
        k_mma<2><<<gridGEMM, NT, GEMM_SMEM>>>(2 * l + 1, b2 + l * HH, nullptr,
                                              bn1g + l * HH, bn1b + l * HH);
    }
    k_pool<<<gridPool, NT>>>(batch, bng + 4 * HH, bnb + 4 * HH);
    k_final<<<GG, HH>>>(cw1, cb1, cw2, cb2, out);
}